// round 4
// baseline (speedup 1.0000x reference)
#include <cuda_runtime.h>
#include <cuda_bf16.h>
#include <stdint.h>

#define NSAMP 8192
#define MAX_IN 8
#define IMG_DIM 3200
#define FC 512
#define NATTR 7
#define NANS 2
#define M1 (NSAMP * 3)

// ---------------- scratch (static device globals; no allocs) ----------------
__device__ __align__(16) float g_feats[M1 * FC];
__device__ __align__(16) float g_x[NSAMP * 2 * FC];
__device__ __align__(16) float g_h[NSAMP * FC];
__device__ int g_counts[NATTR];
__device__ int g_offsets[NATTR];
__device__ int g_cursors[NATTR];
__device__ int g_idx[NSAMP];

// ---------------- grouping: counting sort of samples by attr ----------------
__global__ void k_zero() {
    int t = threadIdx.x;
    if (t < NATTR) { g_counts[t] = 0; g_cursors[t] = 0; }
}
__global__ void k_count(const int* __restrict__ attrs) {
    int n = blockIdx.x * blockDim.x + threadIdx.x;
    if (n < NSAMP) atomicAdd(&g_counts[attrs[n]], 1);
}
__global__ void k_scan() {
    if (threadIdx.x == 0) {
        int o = 0;
        for (int a = 0; a < NATTR; a++) { g_offsets[a] = o; o += g_counts[a]; }
    }
}
__global__ void k_scatter(const int* __restrict__ attrs) {
    int n = blockIdx.x * blockDim.x + threadIdx.x;
    if (n < NSAMP) {
        int a = attrs[n];
        int p = atomicAdd(&g_cursors[a], 1);
        g_idx[g_offsets[a] + p] = n;
    }
}

// ---------------- helpers ----------------
__device__ __forceinline__ void split4_store(float4 v,
                                             __nv_bfloat16* hp,
                                             __nv_bfloat16* lp) {
    __nv_bfloat162 h01, h23, l01, l23;
    h01.x = __float2bfloat16(v.x); h01.y = __float2bfloat16(v.y);
    h23.x = __float2bfloat16(v.z); h23.y = __float2bfloat16(v.w);
    l01.x = __float2bfloat16(v.x - __bfloat162float(h01.x));
    l01.y = __float2bfloat16(v.y - __bfloat162float(h01.y));
    l23.x = __float2bfloat16(v.z - __bfloat162float(h23.x));
    l23.y = __float2bfloat16(v.w - __bfloat162float(h23.y));
    *(__nv_bfloat162*)(hp)     = h01;
    *(__nv_bfloat162*)(hp + 2) = h23;
    *(__nv_bfloat162*)(lp)     = l01;
    *(__nv_bfloat162*)(lp + 2) = l23;
}

__device__ __forceinline__ void mma16816(float* c, const uint32_t* a, const uint32_t* b) {
    asm volatile(
        "mma.sync.aligned.m16n8k16.row.col.f32.bf16.bf16.f32 "
        "{%0,%1,%2,%3}, {%4,%5,%6,%7}, {%8,%9}, {%0,%1,%2,%3};\n"
        : "+f"(c[0]), "+f"(c[1]), "+f"(c[2]), "+f"(c[3])
        : "r"(a[0]), "r"(a[1]), "r"(a[2]), "r"(a[3]), "r"(b[0]), "r"(b[1]));
}

__device__ __forceinline__ void ldsm_x4(uint32_t* r, const void* p) {
    uint32_t a = (uint32_t)__cvta_generic_to_shared(p);
    asm volatile("ldmatrix.sync.aligned.m8n8.x4.shared.b16 {%0,%1,%2,%3}, [%4];"
                 : "=r"(r[0]), "=r"(r[1]), "=r"(r[2]), "=r"(r[3]) : "r"(a));
}
__device__ __forceinline__ void ldsm_x4_t(uint32_t* r, const void* p) {
    uint32_t a = (uint32_t)__cvta_generic_to_shared(p);
    asm volatile("ldmatrix.sync.aligned.m8n8.x4.trans.shared.b16 {%0,%1,%2,%3}, [%4];"
                 : "=r"(r[0]), "=r"(r[1]), "=r"(r[2]), "=r"(r[3]) : "r"(a));
}

// ---------------- GEMM1 (ldmatrix + mma): feats = relu(img@Wcnn + b) --------
// M=24576, K=3200, N=512. Block 128x128x32, 8 warps, warp tile 64x32.
#define BM1 128
#define BN1 128
#define BK1 32
#define ASTR (BK1 + 8)     // 40 el = 80B rows, 16B aligned, LDSM conflict-free
#define BSTR (BN1 + 8)     // 136 el = 272B rows, 16B aligned, conflict-free

__global__ __launch_bounds__(256) void k_gemm1_mma(
    const float* __restrict__ img, const float* __restrict__ W,
    const float* __restrict__ bias)
{
    __shared__ __align__(16) __nv_bfloat16 Ah[BM1][ASTR];
    __shared__ __align__(16) __nv_bfloat16 Al[BM1][ASTR];
    __shared__ __align__(16) __nv_bfloat16 Bh[BK1][BSTR];
    __shared__ __align__(16) __nv_bfloat16 Bl[BK1][BSTR];
    __shared__ const float* rowp[BM1];

    const int tid  = threadIdx.x;
    const int lane = tid & 31;
    const int warp = tid >> 5;
    const int bm0  = blockIdx.y * BM1;
    const int bn0  = blockIdx.x * BN1;
    const int wm = (warp >> 2) * 64;
    const int wn = (warp & 3) * 32;
    const int fr = lane >> 2;
    const int fc = (lane & 3) * 2;

    // ldmatrix lane addressing components
    const int a_row = lane & 15;           // row within 16-row tile
    const int a_ks  = (lane >> 4) * 8;     // k sub-offset 0/8
    const int b_row = (lane & 7) + ((lane >> 3) & 1) * 8;   // k row 0..15
    const int b_cs  = (lane >> 4) * 8;     // n sub-offset 0/8

    if (tid < BM1) {
        int row = bm0 + tid;
        int n = row / 3, s = row - 3 * n;
        rowp[tid] = img + (size_t)(n * MAX_IN + s) * IMG_DIM;
    }
    __syncthreads();

    const int ar = tid >> 3;               // A rows ar + 32r
    const int ak = (tid & 7) * 4;
    const int bk = tid >> 5;               // B k-rows bk + 8r
    const int bc = lane * 4;

    const float* ap[4];
#pragma unroll
    for (int r = 0; r < 4; r++) ap[r] = rowp[ar + r * 32] + ak;
    const float* bp = W + (size_t)bk * FC + bn0 + bc;

    float acc[4][4][4];
#pragma unroll
    for (int mt = 0; mt < 4; mt++)
#pragma unroll
        for (int nt = 0; nt < 4; nt++)
#pragma unroll
            for (int i = 0; i < 4; i++) acc[mt][nt][i] = 0.f;

    float4 sa[4], sb[4];
#pragma unroll
    for (int r = 0; r < 4; r++) sa[r] = *(const float4*)(ap[r]);
#pragma unroll
    for (int r = 0; r < 4; r++) sb[r] = *(const float4*)(bp + (size_t)(r * 8) * FC);

    for (int k0 = 0; k0 < IMG_DIM; k0 += BK1) {
#pragma unroll
        for (int r = 0; r < 4; r++)
            split4_store(sa[r], &Ah[ar + r * 32][ak], &Al[ar + r * 32][ak]);
#pragma unroll
        for (int r = 0; r < 4; r++)
            split4_store(sb[r], &Bh[bk + r * 8][bc], &Bl[bk + r * 8][bc]);
        __syncthreads();

        if (k0 + BK1 < IMG_DIM) {
#pragma unroll
            for (int r = 0; r < 4; r++)
                sa[r] = *(const float4*)(ap[r] + k0 + BK1);
#pragma unroll
            for (int r = 0; r < 4; r++)
                sb[r] = *(const float4*)(bp + (size_t)(k0 + BK1 + r * 8) * FC);
        }

#pragma unroll
        for (int ks = 0; ks < 2; ks++) {
            const int kb = ks * 16;
            uint32_t afh[4][4], afl[4][4], bfh[2][4], bfl[2][4];
#pragma unroll
            for (int mt = 0; mt < 4; mt++) {
                ldsm_x4(afh[mt], &Ah[wm + mt * 16 + a_row][kb + a_ks]);
                ldsm_x4(afl[mt], &Al[wm + mt * 16 + a_row][kb + a_ks]);
            }
#pragma unroll
            for (int np = 0; np < 2; np++) {
                ldsm_x4_t(bfh[np], &Bh[kb + b_row][wn + np * 16 + b_cs]);
                ldsm_x4_t(bfl[np], &Bl[kb + b_row][wn + np * 16 + b_cs]);
            }
#pragma unroll
            for (int mt = 0; mt < 4; mt++)
#pragma unroll
                for (int nt = 0; nt < 4; nt++) {
                    const uint32_t* bh = &bfh[nt >> 1][(nt & 1) * 2];
                    const uint32_t* bl = &bfl[nt >> 1][(nt & 1) * 2];
                    mma16816(acc[mt][nt], afh[mt], bh);
                    mma16816(acc[mt][nt], afh[mt], bl);
                    mma16816(acc[mt][nt], afl[mt], bh);
                }
        }
        __syncthreads();
    }

#pragma unroll
    for (int nt = 0; nt < 4; nt++) {
        int c = bn0 + wn + nt * 8 + fc;
        float b0 = bias[c], b1 = bias[c + 1];
#pragma unroll
        for (int mt = 0; mt < 4; mt++) {
            int r = bm0 + wm + mt * 16 + fr;
            float2 o;
            o.x = fmaxf(acc[mt][nt][0] + b0, 0.f);
            o.y = fmaxf(acc[mt][nt][1] + b1, 0.f);
            *(float2*)(g_feats + (size_t)r * FC + c) = o;
            o.x = fmaxf(acc[mt][nt][2] + b0, 0.f);
            o.y = fmaxf(acc[mt][nt][3] + b1, 0.f);
            *(float2*)(g_feats + (size_t)(r + 8) * FC + c) = o;
        }
    }
}

// ---------------- build x ----------------
__global__ void k_makex(const int* __restrict__ attrs) {
    int i = blockIdx.x * blockDim.x + threadIdx.x;
    if (i >= NSAMP * FC) return;
    int n = i >> 9;
    int k = i & (FC - 1);
    int a = attrs[n];
    bool dist = (a >= 5);
    float f0 = g_feats[(size_t)(n * 3 + 0) * FC + k];
    float f1 = g_feats[(size_t)(n * 3 + 1) * FC + k];
    float f2 = g_feats[(size_t)(n * 3 + 2) * FC + k];
    g_x[(size_t)n * (2 * FC) + k]      = dist ? f0 * f1 : f0;
    g_x[(size_t)n * (2 * FC) + FC + k] = dist ? f1 * f2 : f1;
}

// ---------------- GEMM2 (ldmatrix + mma, grouped, gathered) -----------------
// Block 64x128, K=1024. 8 warps, warp tile 32x32.
#define GM2 64
#define GN2 128
#define GK2 32
#define CHUNKS ((NSAMP + GM2 - 1) / GM2)    // 128

__global__ __launch_bounds__(256) void k_gemm2_mma(
    const float* __restrict__ W1, const float* __restrict__ b1)
{
    const int attr  = blockIdx.x / CHUNKS;
    const int chunk = blockIdx.x % CHUNKS;
    const int cnt   = g_counts[attr];
    if (chunk * GM2 >= cnt) return;
    const int base   = g_offsets[attr] + chunk * GM2;
    const int nvalid = min(GM2, cnt - chunk * GM2);

    __shared__ __align__(16) __nv_bfloat16 Ah[GM2][GK2 + 8];
    __shared__ __align__(16) __nv_bfloat16 Al[GM2][GK2 + 8];
    __shared__ __align__(16) __nv_bfloat16 Bh[GK2][GN2 + 8];
    __shared__ __align__(16) __nv_bfloat16 Bl[GK2][GN2 + 8];
    __shared__ int sid[GM2];

    const int tid  = threadIdx.x;
    const int lane = tid & 31;
    const int warp = tid >> 5;
    const int bn0  = blockIdx.y * GN2;
    const int wm = (warp >> 2) * 32;
    const int wn = (warp & 3) * 32;
    const int fr = lane >> 2;
    const int fc = (lane & 3) * 2;

    const int a_row = lane & 15;
    const int a_ks  = (lane >> 4) * 8;
    const int b_row = (lane & 7) + ((lane >> 3) & 1) * 8;
    const int b_cs  = (lane >> 4) * 8;

    if (tid < GM2) sid[tid] = (tid < nvalid) ? g_idx[base + tid] : -1;
    __syncthreads();

    const float* Wp = W1 + (size_t)attr * (2 * FC) * FC;

    const int ar = tid >> 3;
    const int ak = (tid & 7) * 4;
    const int bk = tid >> 5;
    const int bc = lane * 4;

    const int s0 = sid[ar];
    const int s1 = sid[ar + 32];
    const float* xp0 = g_x + (size_t)(s0 < 0 ? 0 : s0) * (2 * FC) + ak;
    const float* xp1 = g_x + (size_t)(s1 < 0 ? 0 : s1) * (2 * FC) + ak;
    const float* bp  = Wp + (size_t)bk * FC + bn0 + bc;

    float acc[2][4][4];
#pragma unroll
    for (int mt = 0; mt < 2; mt++)
#pragma unroll
        for (int nt = 0; nt < 4; nt++)
#pragma unroll
            for (int i = 0; i < 4; i++) acc[mt][nt][i] = 0.f;

    const float4 z4 = make_float4(0.f, 0.f, 0.f, 0.f);
    float4 sa0, sa1, sb[4];
    sa0 = (s0 >= 0) ? *(const float4*)(xp0) : z4;
    sa1 = (s1 >= 0) ? *(const float4*)(xp1) : z4;
#pragma unroll
    for (int r = 0; r < 4; r++) sb[r] = *(const float4*)(bp + (size_t)(r * 8) * FC);

    for (int k0 = 0; k0 < 2 * FC; k0 += GK2) {
        split4_store(sa0, &Ah[ar][ak],      &Al[ar][ak]);
        split4_store(sa1, &Ah[ar + 32][ak], &Al[ar + 32][ak]);
#pragma unroll
        for (int r = 0; r < 4; r++)
            split4_store(sb[r], &Bh[bk + r * 8][bc], &Bl[bk + r * 8][bc]);
        __syncthreads();

        if (k0 + GK2 < 2 * FC) {
            sa0 = (s0 >= 0) ? *(const float4*)(xp0 + k0 + GK2) : z4;
            sa1 = (s1 >= 0) ? *(const float4*)(xp1 + k0 + GK2) : z4;
#pragma unroll
            for (int r = 0; r < 4; r++)
                sb[r] = *(const float4*)(bp + (size_t)(k0 + GK2 + r * 8) * FC);
        }

#pragma unroll
        for (int ks = 0; ks < 2; ks++) {
            const int kb = ks * 16;
            uint32_t afh[2][4], afl[2][4], bfh[2][4], bfl[2][4];
#pragma unroll
            for (int mt = 0; mt < 2; mt++) {
                ldsm_x4(afh[mt], &Ah[wm + mt * 16 + a_row][kb + a_ks]);
                ldsm_x4(afl[mt], &Al[wm + mt * 16 + a_row][kb + a_ks]);
            }
#pragma unroll
            for (int np = 0; np < 2; np++) {
                ldsm_x4_t(bfh[np], &Bh[kb + b_row][wn + np * 16 + b_cs]);
                ldsm_x4_t(bfl[np], &Bl[kb + b_row][wn + np * 16 + b_cs]);
            }
#pragma unroll
            for (int mt = 0; mt < 2; mt++)
#pragma unroll
                for (int nt = 0; nt < 4; nt++) {
                    const uint32_t* bh = &bfh[nt >> 1][(nt & 1) * 2];
                    const uint32_t* bl = &bfl[nt >> 1][(nt & 1) * 2];
                    mma16816(acc[mt][nt], afh[mt], bh);
                    mma16816(acc[mt][nt], afh[mt], bl);
                    mma16816(acc[mt][nt], afl[mt], bh);
                }
        }
        __syncthreads();
    }

#pragma unroll
    for (int nt = 0; nt < 4; nt++) {
        int c = bn0 + wn + nt * 8 + fc;
        float b0 = b1[(size_t)attr * FC + c];
        float bb = b1[(size_t)attr * FC + c + 1];
#pragma unroll
        for (int mt = 0; mt < 2; mt++) {
            int r = wm + mt * 16 + fr;
            int sA = sid[r];
            int sB = sid[r + 8];
            if (sA >= 0) {
                float2 o;
                o.x = fmaxf(acc[mt][nt][0] + b0, 0.f);
                o.y = fmaxf(acc[mt][nt][1] + bb, 0.f);
                *(float2*)(g_h + (size_t)sA * FC + c) = o;
            }
            if (sB >= 0) {
                float2 o;
                o.x = fmaxf(acc[mt][nt][2] + b0, 0.f);
                o.y = fmaxf(acc[mt][nt][3] + bb, 0.f);
                *(float2*)(g_h + (size_t)sB * FC + c) = o;
            }
        }
    }
}

// ---------------- scores ----------------
__global__ __launch_bounds__(256) void k_out(
    const int* __restrict__ attrs, const float* __restrict__ W2,
    const float* __restrict__ b2, float* __restrict__ out)
{
    int warp = (blockIdx.x * blockDim.x + threadIdx.x) >> 5;
    int lane = threadIdx.x & 31;
    if (warp >= NSAMP) return;
    int n = warp;
    int a = attrs[n];
    const float* w = W2 + (size_t)a * FC * NANS;
    const float* hp = g_h + (size_t)n * FC;
    float s0 = 0.f, s1 = 0.f;
#pragma unroll
    for (int k = lane; k < FC; k += 32) {
        float hv = hp[k];
        s0 += hv * w[k * 2 + 0];
        s1 += hv * w[k * 2 + 1];
    }
#pragma unroll
    for (int o = 16; o; o >>= 1) {
        s0 += __shfl_down_sync(0xffffffffu, s0, o);
        s1 += __shfl_down_sync(0xffffffffu, s1, o);
    }
    if (lane == 0) {
        out[n * 2 + 0] = s0 + b2[a * 2 + 0];
        out[n * 2 + 1] = s1 + b2[a * 2 + 1];
    }
}

// ---------------- launch ----------------
extern "C" void kernel_launch(void* const* d_in, const int* in_sizes, int n_in,
                              void* d_out, int out_size) {
    const float* img   = (const float*)d_in[0];
    const int*   attrs = (const int*)d_in[1];
    const float* Wcnn  = (const float*)d_in[2];
    const float* bcnn  = (const float*)d_in[3];
    const float* W1    = (const float*)d_in[4];
    const float* b1    = (const float*)d_in[5];
    const float* W2    = (const float*)d_in[6];
    const float* b2    = (const float*)d_in[7];
    float* out = (float*)d_out;

    k_zero<<<1, 32>>>();
    k_count<<<(NSAMP + 255) / 256, 256>>>(attrs);
    k_scan<<<1, 32>>>();

    // GEMM1 has no dependency on the sort — launch 4th so ncu (-s 5 offset
    // that landed on position 4 last rounds) captures the hot kernel.
    dim3 g1(FC / BN1, M1 / BM1);
    k_gemm1_mma<<<g1, 256>>>(img, Wcnn, bcnn);

    k_scatter<<<(NSAMP + 255) / 256, 256>>>(attrs);
    k_makex<<<(NSAMP * FC + 255) / 256, 256>>>(attrs);

    dim3 g2(NATTR * CHUNKS, FC / GN2);
    k_gemm2_mma<<<g2, 256>>>(W1, b1);

    k_out<<<NSAMP / 8, 256>>>(attrs, W2, b2, out);
}

// round 6
// speedup vs baseline: 1.3078x; 1.3078x over previous
#include <cuda_runtime.h>
#include <cuda_bf16.h>
#include <stdint.h>

#define NSAMP 8192
#define MAX_IN 8
#define IMG_DIM 3200
#define FC 512
#define NATTR 7
#define NANS 2
#define M1 (NSAMP * 3)

// GEMM tiling (both GEMMs): 128x128 block, BK=32, 512 thr, warp tile 32x32
#define BM 128
#define BN 128
#define BK 32
#define KT1 (IMG_DIM / BK)         // 100
#define KT2 ((2 * FC) / BK)        // 32
#define NSTG 3
#define ASTRIDE 40                 // bf16 elems per A smem row (80 B)
#define BSTRIDE 136                // bf16 elems per B smem row (272 B)
#define OFF_AH 0
#define OFF_AL 10240
#define OFF_BH 20480
#define OFF_BL 29184
#define STAGE 37888
#define SMEM_SZ (NSTG * STAGE)     // 113664
#define GM2 128
#define MAXCH (NSAMP / GM2 + NATTR)  // 71

// ---------------- scratch (static device globals) ----------------
__device__ __align__(16) __nv_bfloat16 g_ah[(size_t)M1 * IMG_DIM];
__device__ __align__(16) __nv_bfloat16 g_al[(size_t)M1 * IMG_DIM];
__device__ __align__(16) __nv_bfloat16 g_wh[(size_t)IMG_DIM * FC];
__device__ __align__(16) __nv_bfloat16 g_wl[(size_t)IMG_DIM * FC];
__device__ __align__(16) __nv_bfloat16 g_w1h[(size_t)NATTR * 2 * FC * FC];
__device__ __align__(16) __nv_bfloat16 g_w1l[(size_t)NATTR * 2 * FC * FC];
__device__ __align__(16) __nv_bfloat16 g_xh[(size_t)NSAMP * 2 * FC];
__device__ __align__(16) __nv_bfloat16 g_xl[(size_t)NSAMP * 2 * FC];
__device__ __align__(16) float g_feats[(size_t)M1 * FC];
__device__ __align__(16) float g_h[(size_t)NSAMP * FC];
__device__ int g_counts[NATTR];
__device__ int g_offsets[NATTR];
__device__ int g_cursors[NATTR];
__device__ int g_chunk_off[NATTR + 1];
__device__ int g_idx[NSAMP];

// ---------------- helpers ----------------
__device__ __forceinline__ void split1(float v, __nv_bfloat16& h, __nv_bfloat16& l) {
    h = __float2bfloat16(v);
    l = __float2bfloat16(v - __bfloat162float(h));
}
__device__ __forceinline__ void split4(float4 v, uint2& hi, uint2& lo) {
    __nv_bfloat162 h01, h23, l01, l23;
    h01.x = __float2bfloat16(v.x); h01.y = __float2bfloat16(v.y);
    h23.x = __float2bfloat16(v.z); h23.y = __float2bfloat16(v.w);
    l01.x = __float2bfloat16(v.x - __bfloat162float(h01.x));
    l01.y = __float2bfloat16(v.y - __bfloat162float(h01.y));
    l23.x = __float2bfloat16(v.z - __bfloat162float(h23.x));
    l23.y = __float2bfloat16(v.w - __bfloat162float(h23.y));
    hi.x = *(uint32_t*)&h01; hi.y = *(uint32_t*)&h23;
    lo.x = *(uint32_t*)&l01; lo.y = *(uint32_t*)&l23;
}
__device__ __forceinline__ void mma16816(float* c, const uint32_t* a, const uint32_t* b) {
    asm volatile(
        "mma.sync.aligned.m16n8k16.row.col.f32.bf16.bf16.f32 "
        "{%0,%1,%2,%3}, {%4,%5,%6,%7}, {%8,%9}, {%0,%1,%2,%3};\n"
        : "+f"(c[0]), "+f"(c[1]), "+f"(c[2]), "+f"(c[3])
        : "r"(a[0]), "r"(a[1]), "r"(a[2]), "r"(a[3]), "r"(b[0]), "r"(b[1]));
}
__device__ __forceinline__ void ldsm_x4(uint32_t* r, uint32_t a) {
    asm volatile("ldmatrix.sync.aligned.m8n8.x4.shared.b16 {%0,%1,%2,%3}, [%4];"
                 : "=r"(r[0]), "=r"(r[1]), "=r"(r[2]), "=r"(r[3]) : "r"(a));
}
__device__ __forceinline__ void ldsm_x4_t(uint32_t* r, uint32_t a) {
    asm volatile("ldmatrix.sync.aligned.m8n8.x4.trans.shared.b16 {%0,%1,%2,%3}, [%4];"
                 : "=r"(r[0]), "=r"(r[1]), "=r"(r[2]), "=r"(r[3]) : "r"(a));
}
__device__ __forceinline__ void cp16(uint32_t dst, const void* src) {
    asm volatile("cp.async.cg.shared.global [%0], [%1], 16;"
                 :: "r"(dst), "l"(src) : "memory");
}
__device__ __forceinline__ void cp16z(uint32_t dst, const void* src, uint32_t sz) {
    asm volatile("cp.async.cg.shared.global [%0], [%1], 16, %2;"
                 :: "r"(dst), "l"(src), "r"(sz) : "memory");
}
__device__ __forceinline__ void cp_commit() {
    asm volatile("cp.async.commit_group;" ::: "memory");
}
__device__ __forceinline__ void cp_wait1() {
    asm volatile("cp.async.wait_group 1;" ::: "memory");
}
__device__ __forceinline__ void cp_wait0() {
    asm volatile("cp.async.wait_group 0;" ::: "memory");
}

// ---------------- small kernels ----------------
__global__ void k_zero() {
    int t = threadIdx.x;
    if (t < NATTR) { g_counts[t] = 0; g_cursors[t] = 0; }
}
__global__ void k_count(const int* __restrict__ attrs) {
    int n = blockIdx.x * blockDim.x + threadIdx.x;
    if (n < NSAMP) atomicAdd(&g_counts[attrs[n]], 1);
}
__global__ void k_scan() {
    if (threadIdx.x == 0) {
        int o = 0, co = 0;
        for (int a = 0; a < NATTR; a++) {
            g_offsets[a] = o;
            g_chunk_off[a] = co;
            o += g_counts[a];
            co += (g_counts[a] + GM2 - 1) / GM2;
        }
        g_chunk_off[NATTR] = co;
    }
}
__global__ void k_scatter(const int* __restrict__ attrs) {
    int n = blockIdx.x * blockDim.x + threadIdx.x;
    if (n < NSAMP) {
        int a = attrs[n];
        int p = atomicAdd(&g_cursors[a], 1);
        g_idx[g_offsets[a] + p] = n;
    }
}

// ---------------- prep: elementwise bf16 hi/lo splits ----------------
__global__ void k_prep_img(const float* __restrict__ img) {
    int idx = blockIdx.x * blockDim.x + threadIdx.x;   // over M1*IMG_DIM/4
    if (idx >= M1 * (IMG_DIM / 4)) return;
    int row = idx / (IMG_DIM / 4);
    int c = idx - row * (IMG_DIM / 4);
    int n = row / 3, s = row - 3 * n;
    float4 v = *(const float4*)(img + (size_t)(n * MAX_IN + s) * IMG_DIM + c * 4);
    uint2 hi, lo;
    split4(v, hi, lo);
    *(uint2*)(g_ah + (size_t)row * IMG_DIM + c * 4) = hi;
    *(uint2*)(g_al + (size_t)row * IMG_DIM + c * 4) = lo;
}
__global__ void k_prep_wcnn(const float* __restrict__ W) {
    int idx = blockIdx.x * blockDim.x + threadIdx.x;   // over IMG_DIM*FC/4
    if (idx >= IMG_DIM * FC / 4) return;
    float4 v = *(const float4*)(W + (size_t)idx * 4);
    uint2 hi, lo;
    split4(v, hi, lo);
    *(uint2*)(g_wh + (size_t)idx * 4) = hi;
    *(uint2*)(g_wl + (size_t)idx * 4) = lo;
}
__global__ void k_prep_w1(const float* __restrict__ W1) {
    int idx = blockIdx.x * blockDim.x + threadIdx.x;   // over NATTR*2FC*FC/4
    if (idx >= NATTR * 2 * FC * FC / 4) return;
    float4 v = *(const float4*)(W1 + (size_t)idx * 4);
    uint2 hi, lo;
    split4(v, hi, lo);
    *(uint2*)(g_w1h + (size_t)idx * 4) = hi;
    *(uint2*)(g_w1l + (size_t)idx * 4) = lo;
}

// ---------------- GEMM1: feats = relu(img3 @ Wcnn + b) ----------------
// 512 thr, 16 warps (4x4 grid of 32x32 warp tiles), cp.async 3-stage pipeline.
__global__ __launch_bounds__(512) void k_gemm1(const float* __restrict__ bias)
{
    extern __shared__ char smem[];
    const uint32_t sb = (uint32_t)__cvta_generic_to_shared(smem);
    const int tid = threadIdx.x, lane = tid & 31, warp = tid >> 5;
    const int bn0 = blockIdx.x * BN, bm0 = blockIdx.y * BM;
    const int wm = (warp >> 2) * 32, wn = (warp & 3) * 32;
    const int fr = lane >> 2, fc = (lane & 3) * 2;
    const int a_row = lane & 15, a_ks = (lane >> 4) * 8;
    const int b_row = (lane & 7) + ((lane >> 3) & 1) * 8, b_cs = (lane >> 4) * 8;

    // cp.async mappings
    const int arow = tid >> 2, ac = tid & 3;            // A: row, 8-el chunk
    const int brow = tid >> 4, bc2 = tid & 15;          // B: k-row, 8-el chunk
    const __nv_bfloat16* sAh = g_ah + (size_t)(bm0 + arow) * IMG_DIM + ac * 8;
    const __nv_bfloat16* sAl = g_al + (size_t)(bm0 + arow) * IMG_DIM + ac * 8;
    const __nv_bfloat16* sBh = g_wh + (size_t)brow * FC + bn0 + bc2 * 8;
    const __nv_bfloat16* sBl = g_wl + (size_t)brow * FC + bn0 + bc2 * 8;
    const uint32_t dA = (uint32_t)(arow * (ASTRIDE * 2) + ac * 16);
    const uint32_t dB = (uint32_t)(brow * (BSTRIDE * 2) + bc2 * 16);

    float acc[2][4][4];
#pragma unroll
    for (int mt = 0; mt < 2; mt++)
#pragma unroll
        for (int nt = 0; nt < 4; nt++)
#pragma unroll
            for (int i = 0; i < 4; i++) acc[mt][nt][i] = 0.f;

#define G1_ISSUE(t_) do {                                        \
        const int buf_ = (t_) % NSTG;                            \
        const uint32_t s_ = sb + buf_ * STAGE;                   \
        const int k0_ = (t_) * BK;                               \
        cp16(s_ + OFF_AH + dA, sAh + k0_);                       \
        cp16(s_ + OFF_AL + dA, sAl + k0_);                       \
        cp16(s_ + OFF_BH + dB, sBh + (size_t)k0_ * FC);          \
        cp16(s_ + OFF_BL + dB, sBl + (size_t)k0_ * FC);          \
        cp_commit();                                             \
    } while (0)

    G1_ISSUE(0);
    G1_ISSUE(1);

    for (int t = 0; t < KT1; t++) {
        if (t < KT1 - 1) cp_wait1(); else cp_wait0();
        __syncthreads();
        if (t + 2 < KT1) G1_ISSUE(t + 2);

        const uint32_t s = sb + (t % NSTG) * STAGE;
#pragma unroll
        for (int ks = 0; ks < 2; ks++) {
            const int kb = ks * 16;
            uint32_t afh[2][4], afl[2][4], bfh[2][4], bfl[2][4];
#pragma unroll
            for (int mt = 0; mt < 2; mt++) {
                uint32_t ra = s + OFF_AH
                    + ((wm + mt * 16 + a_row) * ASTRIDE + kb + a_ks) * 2;
                ldsm_x4(afh[mt], ra);
                ldsm_x4(afl[mt], ra + (OFF_AL - OFF_AH));
            }
#pragma unroll
            for (int np = 0; np < 2; np++) {
                uint32_t rb = s + OFF_BH
                    + ((kb + b_row) * BSTRIDE + wn + np * 16 + b_cs) * 2;
                ldsm_x4_t(bfh[np], rb);
                ldsm_x4_t(bfl[np], rb + (OFF_BL - OFF_BH));
            }
#pragma unroll
            for (int mt = 0; mt < 2; mt++)
#pragma unroll
                for (int nt = 0; nt < 4; nt++) {
                    const uint32_t* bh = &bfh[nt >> 1][(nt & 1) * 2];
                    const uint32_t* bl = &bfl[nt >> 1][(nt & 1) * 2];
                    mma16816(acc[mt][nt], afh[mt], bh);
                    mma16816(acc[mt][nt], afh[mt], bl);
                    mma16816(acc[mt][nt], afl[mt], bh);
                }
        }
        __syncthreads();
    }

#pragma unroll
    for (int nt = 0; nt < 4; nt++) {
        int c = bn0 + wn + nt * 8 + fc;
        float b0 = __ldg(bias + c), b1v = __ldg(bias + c + 1);
#pragma unroll
        for (int mt = 0; mt < 2; mt++) {
            int r = bm0 + wm + mt * 16 + fr;
            float2 o;
            o.x = fmaxf(acc[mt][nt][0] + b0, 0.f);
            o.y = fmaxf(acc[mt][nt][1] + b1v, 0.f);
            *(float2*)(g_feats + (size_t)r * FC + c) = o;
            o.x = fmaxf(acc[mt][nt][2] + b0, 0.f);
            o.y = fmaxf(acc[mt][nt][3] + b1v, 0.f);
            *(float2*)(g_feats + (size_t)(r + 8) * FC + c) = o;
        }
    }
#undef G1_ISSUE
}

// ---------------- build x (bf16 hi/lo directly) ----------------
__global__ void k_makex(const int* __restrict__ attrs) {
    int i = blockIdx.x * blockDim.x + threadIdx.x;
    if (i >= NSAMP * FC) return;
    int n = i >> 9;
    int k = i & (FC - 1);
    bool dist = (attrs[n] >= 5);
    float f0 = g_feats[(size_t)(n * 3 + 0) * FC + k];
    float f1 = g_feats[(size_t)(n * 3 + 1) * FC + k];
    float f2 = g_feats[(size_t)(n * 3 + 2) * FC + k];
    float x0 = dist ? f0 * f1 : f0;
    float x1 = dist ? f1 * f2 : f1;
    __nv_bfloat16 h, l;
    size_t base = (size_t)n * (2 * FC);
    split1(x0, h, l); g_xh[base + k] = h;      g_xl[base + k] = l;
    split1(x1, h, l); g_xh[base + FC + k] = h; g_xl[base + FC + k] = l;
}

// ---------------- GEMM2: h = relu(x @ W1[attr] + b1), grouped+gathered -----
__global__ __launch_bounds__(512) void k_gemm2(const float* __restrict__ b1)
{
    const int y = blockIdx.y;
    if (y >= g_chunk_off[NATTR]) return;
    int attr = 0;
#pragma unroll
    for (int a = 0; a < NATTR; a++)
        if (y >= g_chunk_off[a]) attr = a;
    const int chunk = y - g_chunk_off[attr];
    const int cnt = g_counts[attr];
    const int base = g_offsets[attr] + chunk * GM2;
    const int nvalid = min(GM2, cnt - chunk * GM2);

    extern __shared__ char smem[];
    __shared__ int sid[GM2];
    const uint32_t sb = (uint32_t)__cvta_generic_to_shared(smem);
    const int tid = threadIdx.x, lane = tid & 31, warp = tid >> 5;
    const int bn0 = blockIdx.x * BN;
    const int wm = (warp >> 2) * 32, wn = (warp & 3) * 32;
    const int fr = lane >> 2, fc = (lane & 3) * 2;
    const int a_row = lane & 15, a_ks = (lane >> 4) * 8;
    const int b_row = (lane & 7) + ((lane >> 3) & 1) * 8, b_cs = (lane >> 4) * 8;

    if (tid < GM2) sid[tid] = (tid < nvalid) ? g_idx[base + tid] : -1;
    __syncthreads();

    const int arow = tid >> 2, ac = tid & 3;
    const int brow = tid >> 4, bc2 = tid & 15;
    const int asid = sid[arow];
    const uint32_t asz = (asid >= 0) ? 16u : 0u;
    const __nv_bfloat16* sAh = g_xh + (size_t)(asid < 0 ? 0 : asid) * (2 * FC) + ac * 8;
    const __nv_bfloat16* sAl = g_xl + (size_t)(asid < 0 ? 0 : asid) * (2 * FC) + ac * 8;
    const __nv_bfloat16* sBh = g_w1h + (size_t)attr * 2 * FC * FC
                               + (size_t)brow * FC + bn0 + bc2 * 8;
    const __nv_bfloat16* sBl = g_w1l + (size_t)attr * 2 * FC * FC
                               + (size_t)brow * FC + bn0 + bc2 * 8;
    const uint32_t dA = (uint32_t)(arow * (ASTRIDE * 2) + ac * 16);
    const uint32_t dB = (uint32_t)(brow * (BSTRIDE * 2) + bc2 * 16);

    float acc[2][4][4];
#pragma unroll
    for (int mt = 0; mt < 2; mt++)
#pragma unroll
        for (int nt = 0; nt < 4; nt++)
#pragma unroll
            for (int i = 0; i < 4; i++) acc[mt][nt][i] = 0.f;

#define G2_ISSUE(t_) do {                                        \
        const int buf_ = (t_) % NSTG;                            \
        const uint32_t s_ = sb + buf_ * STAGE;                   \
        const int k0_ = (t_) * BK;                               \
        cp16z(s_ + OFF_AH + dA, sAh + k0_, asz);                 \
        cp16z(s_ + OFF_AL + dA, sAl + k0_, asz);                 \
        cp16(s_ + OFF_BH + dB, sBh + (size_t)k0_ * FC);          \
        cp16(s_ + OFF_BL + dB, sBl + (size_t)k0_ * FC);          \
        cp_commit();                                             \
    } while (0)

    G2_ISSUE(0);
    G2_ISSUE(1);

    for (int t = 0; t < KT2; t++) {
        if (t < KT2 - 1) cp_wait1(); else cp_wait0();
        __syncthreads();
        if (t + 2 < KT2) G2_ISSUE(t + 2);

        const uint32_t s = sb + (t % NSTG) * STAGE;
#pragma unroll
        for (int ks = 0; ks < 2; ks++) {
            const int kb = ks * 16;
            uint32_t afh[2][4], afl[2][4], bfh[2][4], bfl[2][4];
#pragma unroll
            for (int mt = 0; mt < 2; mt++) {
                uint32_t ra = s + OFF_AH
                    + ((wm + mt * 16 + a_row) * ASTRIDE + kb + a_ks) * 2;
                ldsm_x4(afh[mt], ra);
                ldsm_x4(afl[mt], ra + (OFF_AL - OFF_AH));
            }
#pragma unroll
            for (int np = 0; np < 2; np++) {
                uint32_t rb = s + OFF_BH
                    + ((kb + b_row) * BSTRIDE + wn + np * 16 + b_cs) * 2;
                ldsm_x4_t(bfh[np], rb);
                ldsm_x4_t(bfl[np], rb + (OFF_BL - OFF_BH));
            }
#pragma unroll
            for (int mt = 0; mt < 2; mt++)
#pragma unroll
                for (int nt = 0; nt < 4; nt++) {
                    const uint32_t* bh = &bfh[nt >> 1][(nt & 1) * 2];
                    const uint32_t* bl = &bfl[nt >> 1][(nt & 1) * 2];
                    mma16816(acc[mt][nt], afh[mt], bh);
                    mma16816(acc[mt][nt], afh[mt], bl);
                    mma16816(acc[mt][nt], afl[mt], bh);
                }
        }
        __syncthreads();
    }

#pragma unroll
    for (int nt = 0; nt < 4; nt++) {
        int c = bn0 + wn + nt * 8 + fc;
        float b0 = __ldg(b1 + (size_t)attr * FC + c);
        float b1v = __ldg(b1 + (size_t)attr * FC + c + 1);
#pragma unroll
        for (int mt = 0; mt < 2; mt++) {
            int rA = wm + mt * 16 + fr;
            int sA = sid[rA], sB = sid[rA + 8];
            if (sA >= 0) {
                float2 o;
                o.x = fmaxf(acc[mt][nt][0] + b0, 0.f);
                o.y = fmaxf(acc[mt][nt][1] + b1v, 0.f);
                *(float2*)(g_h + (size_t)sA * FC + c) = o;
            }
            if (sB >= 0) {
                float2 o;
                o.x = fmaxf(acc[mt][nt][2] + b0, 0.f);
                o.y = fmaxf(acc[mt][nt][3] + b1v, 0.f);
                *(float2*)(g_h + (size_t)sB * FC + c) = o;
            }
        }
    }
#undef G2_ISSUE
}

// ---------------- scores = h @ W2[attr] + b2 ----------------
__global__ __launch_bounds__(256) void k_out(
    const int* __restrict__ attrs, const float* __restrict__ W2,
    const float* __restrict__ b2, float* __restrict__ out)
{
    int warp = (blockIdx.x * blockDim.x + threadIdx.x) >> 5;
    int lane = threadIdx.x & 31;
    if (warp >= NSAMP) return;
    int n = warp;
    int a = attrs[n];
    const float* w = W2 + (size_t)a * FC * NANS;
    const float* hp = g_h + (size_t)n * FC;
    float s0 = 0.f, s1 = 0.f;
#pragma unroll
    for (int k = lane; k < FC; k += 32) {
        float hv = hp[k];
        s0 += hv * w[k * 2 + 0];
        s1 += hv * w[k * 2 + 1];
    }
#pragma unroll
    for (int o = 16; o; o >>= 1) {
        s0 += __shfl_down_sync(0xffffffffu, s0, o);
        s1 += __shfl_down_sync(0xffffffffu, s1, o);
    }
    if (lane == 0) {
        out[n * 2 + 0] = s0 + b2[a * 2 + 0];
        out[n * 2 + 1] = s1 + b2[a * 2 + 1];
    }
}

// ---------------- launch ----------------
extern "C" void kernel_launch(void* const* d_in, const int* in_sizes, int n_in,
                              void* d_out, int out_size) {
    const float* img   = (const float*)d_in[0];
    const int*   attrs = (const int*)d_in[1];
    const float* Wcnn  = (const float*)d_in[2];
    const float* bcnn  = (const float*)d_in[3];
    const float* W1    = (const float*)d_in[4];
    const float* b1    = (const float*)d_in[5];
    const float* W2    = (const float*)d_in[6];
    const float* b2    = (const float*)d_in[7];
    float* out = (float*)d_out;

    cudaFuncSetAttribute(k_gemm1, cudaFuncAttributeMaxDynamicSharedMemorySize, SMEM_SZ);
    cudaFuncSetAttribute(k_gemm2, cudaFuncAttributeMaxDynamicSharedMemorySize, SMEM_SZ);

    // prep (1..3), then GEMM1 in launch slot 4 for ncu capture
    k_prep_img<<<(M1 * (IMG_DIM / 4) + 255) / 256, 256>>>(img);
    k_prep_wcnn<<<(IMG_DIM * FC / 4 + 255) / 256, 256>>>(Wcnn);
    k_zero<<<1, 32>>>();

    k_gemm1<<<dim3(FC / BN, M1 / BM), 512, SMEM_SZ>>>(bcnn);

    k_count<<<(NSAMP + 255) / 256, 256>>>(attrs);
    k_scan<<<1, 32>>>();
    k_scatter<<<(NSAMP + 255) / 256, 256>>>(attrs);
    k_prep_w1<<<(NATTR * 2 * FC * FC / 4 + 255) / 256, 256>>>(W1);
    k_makex<<<(NSAMP * FC + 255) / 256, 256>>>(attrs);

    k_gemm2<<<dim3(FC / BN, MAXCH), 512, SMEM_SZ>>>(b1);

    k_out<<<NSAMP / 8, 256>>>(attrs, W2, b2, out);
}

// round 7
// speedup vs baseline: 1.8675x; 1.4280x over previous
#include <cuda_runtime.h>
#include <cuda_fp16.h>
#include <stdint.h>

#define NSAMP 8192
#define MAX_IN 8
#define IMG_DIM 3200
#define FC 512
#define NATTR 7
#define NANS 2
#define M1 (NSAMP * 3)

// GEMM tiling: 128x128 block, BK=32, 512 thr, warp tile 32x32
#define BM 128
#define BN 128
#define BK 32
#define KT1 (IMG_DIM / BK)         // 100
#define KT2 ((2 * FC) / BK)        // 32
#define NSTG 4
#define ASTRIDE 40                 // fp16 elems per A smem row (80 B)
#define BSTRIDE 136                // fp16 elems per B smem row (272 B)
#define OFF_A  0                   // A: 128 * 80  = 10240 B
#define OFF_BH 10240               // B: 32 * 272  =  8704 B
#define OFF_BL 18944
#define STAGE  27648
#define SMEM_SZ (NSTG * STAGE)     // 110592
#define GM2 128
#define MAXCH (NSAMP / GM2 + NATTR)  // 71

// ---------------- scratch (static device globals) ----------------
__device__ __align__(16) __half g_af[(size_t)M1 * IMG_DIM];        // A fp16 (single)
__device__ __align__(16) __half g_wh[(size_t)IMG_DIM * FC];        // Wcnn hi
__device__ __align__(16) __half g_wl[(size_t)IMG_DIM * FC];        // Wcnn lo
__device__ __align__(16) __half g_w1h[(size_t)NATTR * 2 * FC * FC];
__device__ __align__(16) __half g_w1l[(size_t)NATTR * 2 * FC * FC];
__device__ __align__(16) __half g_xf[(size_t)NSAMP * 2 * FC];      // x fp16 (single)
__device__ __align__(16) float g_feats[(size_t)M1 * FC];
__device__ __align__(16) float g_h[(size_t)NSAMP * FC];
__device__ int g_counts[NATTR];
__device__ int g_offsets[NATTR];
__device__ int g_cursors[NATTR];
__device__ int g_chunk_off[NATTR + 1];
__device__ int g_idx[NSAMP];

// ---------------- helpers ----------------
__device__ __forceinline__ uint2 pack4h(float4 v) {
    __half2 a = __floats2half2_rn(v.x, v.y);
    __half2 b = __floats2half2_rn(v.z, v.w);
    uint2 r;
    r.x = *(uint32_t*)&a;
    r.y = *(uint32_t*)&b;
    return r;
}
__device__ __forceinline__ void split4h(float4 v, uint2& hi, uint2& lo) {
    __half2 h01 = __floats2half2_rn(v.x, v.y);
    __half2 h23 = __floats2half2_rn(v.z, v.w);
    float2 f01 = __half22float2(h01);
    float2 f23 = __half22float2(h23);
    __half2 l01 = __floats2half2_rn(v.x - f01.x, v.y - f01.y);
    __half2 l23 = __floats2half2_rn(v.z - f23.x, v.w - f23.y);
    hi.x = *(uint32_t*)&h01; hi.y = *(uint32_t*)&h23;
    lo.x = *(uint32_t*)&l01; lo.y = *(uint32_t*)&l23;
}
// NOTE: intentionally NOT volatile — pure register math, ptxas may schedule.
__device__ __forceinline__ void mma16816(float* c, const uint32_t* a, const uint32_t* b) {
    asm("mma.sync.aligned.m16n8k16.row.col.f32.f16.f16.f32 "
        "{%0,%1,%2,%3}, {%4,%5,%6,%7}, {%8,%9}, {%0,%1,%2,%3};\n"
        : "+f"(c[0]), "+f"(c[1]), "+f"(c[2]), "+f"(c[3])
        : "r"(a[0]), "r"(a[1]), "r"(a[2]), "r"(a[3]), "r"(b[0]), "r"(b[1]));
}
__device__ __forceinline__ void ldsm_x4(uint32_t* r, uint32_t a) {
    asm volatile("ldmatrix.sync.aligned.m8n8.x4.shared.b16 {%0,%1,%2,%3}, [%4];"
                 : "=r"(r[0]), "=r"(r[1]), "=r"(r[2]), "=r"(r[3]) : "r"(a));
}
__device__ __forceinline__ void ldsm_x4_t(uint32_t* r, uint32_t a) {
    asm volatile("ldmatrix.sync.aligned.m8n8.x4.trans.shared.b16 {%0,%1,%2,%3}, [%4];"
                 : "=r"(r[0]), "=r"(r[1]), "=r"(r[2]), "=r"(r[3]) : "r"(a));
}
__device__ __forceinline__ void cp16(uint32_t dst, const void* src) {
    asm volatile("cp.async.cg.shared.global [%0], [%1], 16;"
                 :: "r"(dst), "l"(src) : "memory");
}
__device__ __forceinline__ void cp16z(uint32_t dst, const void* src, uint32_t sz) {
    asm volatile("cp.async.cg.shared.global [%0], [%1], 16, %2;"
                 :: "r"(dst), "l"(src), "r"(sz) : "memory");
}
__device__ __forceinline__ void cp_commit() {
    asm volatile("cp.async.commit_group;" ::: "memory");
}
__device__ __forceinline__ void cp_wait2() {
    asm volatile("cp.async.wait_group 2;" ::: "memory");
}
__device__ __forceinline__ void cp_wait1() {
    asm volatile("cp.async.wait_group 1;" ::: "memory");
}
__device__ __forceinline__ void cp_wait0() {
    asm volatile("cp.async.wait_group 0;" ::: "memory");
}

// ---------------- small kernels ----------------
__global__ void k_zero() {
    int t = threadIdx.x;
    if (t < NATTR) { g_counts[t] = 0; g_cursors[t] = 0; }
}
__global__ void k_count(const int* __restrict__ attrs) {
    int n = blockIdx.x * blockDim.x + threadIdx.x;
    if (n < NSAMP) atomicAdd(&g_counts[attrs[n]], 1);
}
__global__ void k_scan() {
    if (threadIdx.x == 0) {
        int o = 0, co = 0;
        for (int a = 0; a < NATTR; a++) {
            g_offsets[a] = o;
            g_chunk_off[a] = co;
            o += g_counts[a];
            co += (g_counts[a] + GM2 - 1) / GM2;
        }
        g_chunk_off[NATTR] = co;
    }
}
__global__ void k_scatter(const int* __restrict__ attrs) {
    int n = blockIdx.x * blockDim.x + threadIdx.x;
    if (n < NSAMP) {
        int a = attrs[n];
        int p = atomicAdd(&g_cursors[a], 1);
        g_idx[g_offsets[a] + p] = n;
    }
}

// ---------------- prep kernels ----------------
__global__ void k_prep_img(const float* __restrict__ img) {
    int idx = blockIdx.x * blockDim.x + threadIdx.x;
    if (idx >= M1 * (IMG_DIM / 4)) return;
    int row = idx / (IMG_DIM / 4);
    int c = idx - row * (IMG_DIM / 4);
    int n = row / 3, s = row - 3 * n;
    float4 v = *(const float4*)(img + (size_t)(n * MAX_IN + s) * IMG_DIM + c * 4);
    *(uint2*)(g_af + (size_t)row * IMG_DIM + c * 4) = pack4h(v);
}
__global__ void k_prep_wcnn(const float* __restrict__ W) {
    int idx = blockIdx.x * blockDim.x + threadIdx.x;
    if (idx >= IMG_DIM * FC / 4) return;
    float4 v = *(const float4*)(W + (size_t)idx * 4);
    uint2 hi, lo;
    split4h(v, hi, lo);
    *(uint2*)(g_wh + (size_t)idx * 4) = hi;
    *(uint2*)(g_wl + (size_t)idx * 4) = lo;
}
__global__ void k_prep_w1(const float* __restrict__ W1) {
    int idx = blockIdx.x * blockDim.x + threadIdx.x;
    if (idx >= NATTR * 2 * FC * FC / 4) return;
    float4 v = *(const float4*)(W1 + (size_t)idx * 4);
    uint2 hi, lo;
    split4h(v, hi, lo);
    *(uint2*)(g_w1h + (size_t)idx * 4) = hi;
    *(uint2*)(g_w1l + (size_t)idx * 4) = lo;
}

// ---------------- GEMM1: feats = relu(img3 @ Wcnn + b) ----------------
__global__ __launch_bounds__(512) void k_gemm1(const float* __restrict__ bias)
{
    extern __shared__ char smem[];
    const uint32_t sb = (uint32_t)__cvta_generic_to_shared(smem);
    const int tid = threadIdx.x, lane = tid & 31, warp = tid >> 5;
    const int bn0 = blockIdx.x * BN, bm0 = blockIdx.y * BM;
    const int wm = (warp >> 2) * 32, wn = (warp & 3) * 32;
    const int fr = lane >> 2, fc = (lane & 3) * 2;
    const int a_row = lane & 15, a_ks = (lane >> 4) * 8;
    const int b_row = (lane & 7) + ((lane >> 3) & 1) * 8, b_cs = (lane >> 4) * 8;

    // cp.async mappings: A 8192B (1 cp/thread), B 2x8192B (2 cp/thread)
    const int arow = tid >> 2, ac = tid & 3;
    const int brow = tid >> 4, bc2 = tid & 15;
    const __half* sA  = g_af + (size_t)(bm0 + arow) * IMG_DIM + ac * 8;
    const __half* sBh = g_wh + (size_t)brow * FC + bn0 + bc2 * 8;
    const __half* sBl = g_wl + (size_t)brow * FC + bn0 + bc2 * 8;
    const uint32_t dA = (uint32_t)(arow * (ASTRIDE * 2) + ac * 16);
    const uint32_t dB = (uint32_t)(brow * (BSTRIDE * 2) + bc2 * 16);

    float acc[2][4][4];
#pragma unroll
    for (int mt = 0; mt < 2; mt++)
#pragma unroll
        for (int nt = 0; nt < 4; nt++)
#pragma unroll
            for (int i = 0; i < 4; i++) acc[mt][nt][i] = 0.f;

#define G1_ISSUE(t_) do {                                        \
        const uint32_t s_ = sb + ((t_) % NSTG) * STAGE;          \
        const int k0_ = (t_) * BK;                               \
        cp16(s_ + OFF_A + dA, sA + k0_);                         \
        cp16(s_ + OFF_BH + dB, sBh + (size_t)k0_ * FC);          \
        cp16(s_ + OFF_BL + dB, sBl + (size_t)k0_ * FC);          \
        cp_commit();                                             \
    } while (0)

    G1_ISSUE(0); G1_ISSUE(1); G1_ISSUE(2);

    for (int t = 0; t < KT1; t++) {
        if (t < KT1 - 2) cp_wait2();
        else if (t == KT1 - 2) cp_wait1();
        else cp_wait0();
        __syncthreads();
        if (t + 3 < KT1) G1_ISSUE(t + 3);

        const uint32_t s = sb + (t % NSTG) * STAGE;
#pragma unroll
        for (int ks = 0; ks < 2; ks++) {
            const int kb = ks * 16;
            uint32_t af[2][4], bfh[2][4], bfl[2][4];
#pragma unroll
            for (int mt = 0; mt < 2; mt++)
                ldsm_x4(af[mt], s + OFF_A
                        + ((wm + mt * 16 + a_row) * ASTRIDE + kb + a_ks) * 2);
#pragma unroll
            for (int np = 0; np < 2; np++) {
                uint32_t rb = s + OFF_BH
                    + ((kb + b_row) * BSTRIDE + wn + np * 16 + b_cs) * 2;
                ldsm_x4_t(bfh[np], rb);
                ldsm_x4_t(bfl[np], rb + (OFF_BL - OFF_BH));
            }
            // term-major: 8 independent MMAs per term
#pragma unroll
            for (int mt = 0; mt < 2; mt++)
#pragma unroll
                for (int nt = 0; nt < 4; nt++)
                    mma16816(acc[mt][nt], af[mt], &bfh[nt >> 1][(nt & 1) * 2]);
#pragma unroll
            for (int mt = 0; mt < 2; mt++)
#pragma unroll
                for (int nt = 0; nt < 4; nt++)
                    mma16816(acc[mt][nt], af[mt], &bfl[nt >> 1][(nt & 1) * 2]);
        }
    }

#pragma unroll
    for (int nt = 0; nt < 4; nt++) {
        int c = bn0 + wn + nt * 8 + fc;
        float b0 = __ldg(bias + c), b1v = __ldg(bias + c + 1);
#pragma unroll
        for (int mt = 0; mt < 2; mt++) {
            int r = bm0 + wm + mt * 16 + fr;
            float2 o;
            o.x = fmaxf(acc[mt][nt][0] + b0, 0.f);
            o.y = fmaxf(acc[mt][nt][1] + b1v, 0.f);
            *(float2*)(g_feats + (size_t)r * FC + c) = o;
            o.x = fmaxf(acc[mt][nt][2] + b0, 0.f);
            o.y = fmaxf(acc[mt][nt][3] + b1v, 0.f);
            *(float2*)(g_feats + (size_t)(r + 8) * FC + c) = o;
        }
    }
#undef G1_ISSUE
}

// ---------------- build x (fp16 single) ----------------
__global__ void k_makex(const int* __restrict__ attrs) {
    int i = blockIdx.x * blockDim.x + threadIdx.x;
    if (i >= NSAMP * FC) return;
    int n = i >> 9;
    int k = i & (FC - 1);
    bool dist = (attrs[n] >= 5);
    float f0 = g_feats[(size_t)(n * 3 + 0) * FC + k];
    float f1 = g_feats[(size_t)(n * 3 + 1) * FC + k];
    float f2 = g_feats[(size_t)(n * 3 + 2) * FC + k];
    float x0 = dist ? f0 * f1 : f0;
    float x1 = dist ? f1 * f2 : f1;
    size_t base = (size_t)n * (2 * FC);
    g_xf[base + k]      = __float2half_rn(x0);
    g_xf[base + FC + k] = __float2half_rn(x1);
}

// ---------------- GEMM2: h = relu(x @ W1[attr] + b1), grouped+gathered -----
__global__ __launch_bounds__(512) void k_gemm2(const float* __restrict__ b1)
{
    const int y = blockIdx.y;
    if (y >= g_chunk_off[NATTR]) return;
    int attr = 0;
#pragma unroll
    for (int a = 0; a < NATTR; a++)
        if (y >= g_chunk_off[a]) attr = a;
    const int chunk = y - g_chunk_off[attr];
    const int cnt = g_counts[attr];
    const int base = g_offsets[attr] + chunk * GM2;
    const int nvalid = min(GM2, cnt - chunk * GM2);

    extern __shared__ char smem[];
    __shared__ int sid[GM2];
    const uint32_t sb = (uint32_t)__cvta_generic_to_shared(smem);
    const int tid = threadIdx.x, lane = tid & 31, warp = tid >> 5;
    const int bn0 = blockIdx.x * BN;
    const int wm = (warp >> 2) * 32, wn = (warp & 3) * 32;
    const int fr = lane >> 2, fc = (lane & 3) * 2;
    const int a_row = lane & 15, a_ks = (lane >> 4) * 8;
    const int b_row = (lane & 7) + ((lane >> 3) & 1) * 8, b_cs = (lane >> 4) * 8;

    if (tid < GM2) sid[tid] = (tid < nvalid) ? g_idx[base + tid] : -1;
    __syncthreads();

    const int arow = tid >> 2, ac = tid & 3;
    const int brow = tid >> 4, bc2 = tid & 15;
    const int asid = sid[arow];
    const uint32_t asz = (asid >= 0) ? 16u : 0u;
    const __half* sA  = g_xf + (size_t)(asid < 0 ? 0 : asid) * (2 * FC) + ac * 8;
    const __half* sBh = g_w1h + (size_t)attr * 2 * FC * FC
                        + (size_t)brow * FC + bn0 + bc2 * 8;
    const __half* sBl = g_w1l + (size_t)attr * 2 * FC * FC
                        + (size_t)brow * FC + bn0 + bc2 * 8;
    const uint32_t dA = (uint32_t)(arow * (ASTRIDE * 2) + ac * 16);
    const uint32_t dB = (uint32_t)(brow * (BSTRIDE * 2) + bc2 * 16);

    float acc[2][4][4];
#pragma unroll
    for (int mt = 0; mt < 2; mt++)
#pragma unroll
        for (int nt = 0; nt < 4; nt++)
#pragma unroll
            for (int i = 0; i < 4; i++) acc[mt][nt][i] = 0.f;

#define G2_ISSUE(t_) do {                                        \
        const uint32_t s_ = sb + ((t_) % NSTG) * STAGE;          \
        const int k0_ = (t_) * BK;                               \
        cp16z(s_ + OFF_A + dA, sA + k0_, asz);                   \
        cp16(s_ + OFF_BH + dB, sBh + (size_t)k0_ * FC);          \
        cp16(s_ + OFF_BL + dB, sBl + (size_t)k0_ * FC);          \
        cp_commit();                                             \
    } while (0)

    G2_ISSUE(0); G2_ISSUE(1); G2_ISSUE(2);

    for (int t = 0; t < KT2; t++) {
        if (t < KT2 - 2) cp_wait2();
        else if (t == KT2 - 2) cp_wait1();
        else cp_wait0();
        __syncthreads();
        if (t + 3 < KT2) G2_ISSUE(t + 3);

        const uint32_t s = sb + (t % NSTG) * STAGE;
#pragma unroll
        for (int ks = 0; ks < 2; ks++) {
            const int kb = ks * 16;
            uint32_t af[2][4], bfh[2][4], bfl[2][4];
#pragma unroll
            for (int mt = 0; mt < 2; mt++)
                ldsm_x4(af[mt], s + OFF_A
                        + ((wm + mt * 16 + a_row) * ASTRIDE + kb + a_ks) * 2);
#pragma unroll
            for (int np = 0; np < 2; np++) {
                uint32_t rb = s + OFF_BH
                    + ((kb + b_row) * BSTRIDE + wn + np * 16 + b_cs) * 2;
                ldsm_x4_t(bfh[np], rb);
                ldsm_x4_t(bfl[np], rb + (OFF_BL - OFF_BH));
            }
#pragma unroll
            for (int mt = 0; mt < 2; mt++)
#pragma unroll
                for (int nt = 0; nt < 4; nt++)
                    mma16816(acc[mt][nt], af[mt], &bfh[nt >> 1][(nt & 1) * 2]);
#pragma unroll
            for (int mt = 0; mt < 2; mt++)
#pragma unroll
                for (int nt = 0; nt < 4; nt++)
                    mma16816(acc[mt][nt], af[mt], &bfl[nt >> 1][(nt & 1) * 2]);
        }
    }

#pragma unroll
    for (int nt = 0; nt < 4; nt++) {
        int c = bn0 + wn + nt * 8 + fc;
        float b0 = __ldg(b1 + (size_t)attr * FC + c);
        float b1v = __ldg(b1 + (size_t)attr * FC + c + 1);
#pragma unroll
        for (int mt = 0; mt < 2; mt++) {
            int rA = wm + mt * 16 + fr;
            int sA2 = sid[rA], sB2 = sid[rA + 8];
            if (sA2 >= 0) {
                float2 o;
                o.x = fmaxf(acc[mt][nt][0] + b0, 0.f);
                o.y = fmaxf(acc[mt][nt][1] + b1v, 0.f);
                *(float2*)(g_h + (size_t)sA2 * FC + c) = o;
            }
            if (sB2 >= 0) {
                float2 o;
                o.x = fmaxf(acc[mt][nt][2] + b0, 0.f);
                o.y = fmaxf(acc[mt][nt][3] + b1v, 0.f);
                *(float2*)(g_h + (size_t)sB2 * FC + c) = o;
            }
        }
    }
#undef G2_ISSUE
}

// ---------------- scores = h @ W2[attr] + b2 ----------------
__global__ __launch_bounds__(256) void k_out(
    const int* __restrict__ attrs, const float* __restrict__ W2,
    const float* __restrict__ b2, float* __restrict__ out)
{
    int warp = (blockIdx.x * blockDim.x + threadIdx.x) >> 5;
    int lane = threadIdx.x & 31;
    if (warp >= NSAMP) return;
    int n = warp;
    int a = attrs[n];
    const float* w = W2 + (size_t)a * FC * NANS;
    const float* hp = g_h + (size_t)n * FC;
    float s0 = 0.f, s1 = 0.f;
#pragma unroll
    for (int k = lane; k < FC; k += 32) {
        float hv = hp[k];
        s0 += hv * w[k * 2 + 0];
        s1 += hv * w[k * 2 + 1];
    }
#pragma unroll
    for (int o = 16; o; o >>= 1) {
        s0 += __shfl_down_sync(0xffffffffu, s0, o);
        s1 += __shfl_down_sync(0xffffffffu, s1, o);
    }
    if (lane == 0) {
        out[n * 2 + 0] = s0 + b2[a * 2 + 0];
        out[n * 2 + 1] = s1 + b2[a * 2 + 1];
    }
}

// ---------------- launch ----------------
extern "C" void kernel_launch(void* const* d_in, const int* in_sizes, int n_in,
                              void* d_out, int out_size) {
    const float* img   = (const float*)d_in[0];
    const int*   attrs = (const int*)d_in[1];
    const float* Wcnn  = (const float*)d_in[2];
    const float* bcnn  = (const float*)d_in[3];
    const float* W1    = (const float*)d_in[4];
    const float* b1    = (const float*)d_in[5];
    const float* W2    = (const float*)d_in[6];
    const float* b2    = (const float*)d_in[7];
    float* out = (float*)d_out;

    cudaFuncSetAttribute(k_gemm1, cudaFuncAttributeMaxDynamicSharedMemorySize, SMEM_SZ);
    cudaFuncSetAttribute(k_gemm2, cudaFuncAttributeMaxDynamicSharedMemorySize, SMEM_SZ);

    // prep (slots 1..3), GEMM1 in slot 4 for ncu capture
    k_prep_img<<<(M1 * (IMG_DIM / 4) + 255) / 256, 256>>>(img);
    k_prep_wcnn<<<(IMG_DIM * FC / 4 + 255) / 256, 256>>>(Wcnn);
    k_zero<<<1, 32>>>();

    k_gemm1<<<dim3(FC / BN, M1 / BM), 512, SMEM_SZ>>>(bcnn);

    k_count<<<(NSAMP + 255) / 256, 256>>>(attrs);
    k_scan<<<1, 32>>>();
    k_scatter<<<(NSAMP + 255) / 256, 256>>>(attrs);
    k_prep_w1<<<(NATTR * 2 * FC * FC / 4 + 255) / 256, 256>>>(W1);
    k_makex<<<(NSAMP * FC + 255) / 256, 256>>>(attrs);

    k_gemm2<<<dim3(FC / BN, MAXCH), 512, SMEM_SZ>>>(b1);

    k_out<<<NSAMP / 8, 256>>>(attrs, W2, b2, out);
}

// round 8
// speedup vs baseline: 1.9945x; 1.0680x over previous
#include <cuda_runtime.h>
#include <cuda_fp16.h>
#include <stdint.h>

#define NSAMP 8192
#define MAX_IN 8
#define IMG_DIM 3200
#define FC 512
#define NATTR 7
#define NANS 2
#define M1 (NSAMP * 3)

// GEMM tiling: 128x64 block, BK=32, 256 thr (8 warps, 4Mx2N of 32x32 tiles)
#define BM 128
#define BN 64
#define BK 32
#define KT1 (IMG_DIM / BK)         // 100
#define KT2 ((2 * FC) / BK)        // 32
#define NSTG 4
#define ASTRIDE 40                 // fp16 elems per A smem row (80 B)
#define BSTRIDE 72                 // fp16 elems per B smem row (144 B)
#define OFF_A  0                   // A: 128 * 80 = 10240 B
#define OFF_BH 10240               // B: 32 * 144 = 4608 B each
#define OFF_BL 14848
#define STAGE  19456
#define SMEM_SZ (NSTG * STAGE)     // 77824 -> 2 CTAs/SM
#define GM2 128
#define MAXCH (NSAMP / GM2 + NATTR)  // 71

// ---------------- scratch (static device globals) ----------------
__device__ __align__(16) __half g_af[(size_t)M1 * IMG_DIM];
__device__ __align__(16) __half g_wh[(size_t)IMG_DIM * FC];
__device__ __align__(16) __half g_wl[(size_t)IMG_DIM * FC];
__device__ __align__(16) __half g_w1h[(size_t)NATTR * 2 * FC * FC];
__device__ __align__(16) __half g_w1l[(size_t)NATTR * 2 * FC * FC];
__device__ __align__(16) __half g_xf[(size_t)NSAMP * 2 * FC];
__device__ __align__(16) float g_feats[(size_t)M1 * FC];
__device__ __align__(16) float g_h[(size_t)NSAMP * FC];
__device__ int g_counts[NATTR];
__device__ int g_offsets[NATTR];
__device__ int g_cursors[NATTR];
__device__ int g_chunk_off[NATTR + 1];
__device__ int g_idx[NSAMP];

// ---------------- helpers ----------------
__device__ __forceinline__ uint2 pack4h(float4 v) {
    __half2 a = __floats2half2_rn(v.x, v.y);
    __half2 b = __floats2half2_rn(v.z, v.w);
    uint2 r;
    r.x = *(uint32_t*)&a;
    r.y = *(uint32_t*)&b;
    return r;
}
__device__ __forceinline__ void split4h(float4 v, uint2& hi, uint2& lo) {
    __half2 h01 = __floats2half2_rn(v.x, v.y);
    __half2 h23 = __floats2half2_rn(v.z, v.w);
    float2 f01 = __half22float2(h01);
    float2 f23 = __half22float2(h23);
    __half2 l01 = __floats2half2_rn(v.x - f01.x, v.y - f01.y);
    __half2 l23 = __floats2half2_rn(v.z - f23.x, v.w - f23.y);
    hi.x = *(uint32_t*)&h01; hi.y = *(uint32_t*)&h23;
    lo.x = *(uint32_t*)&l01; lo.y = *(uint32_t*)&l23;
}
__device__ __forceinline__ void mma16816(float* c, const uint32_t* a, const uint32_t* b) {
    asm("mma.sync.aligned.m16n8k16.row.col.f32.f16.f16.f32 "
        "{%0,%1,%2,%3}, {%4,%5,%6,%7}, {%8,%9}, {%0,%1,%2,%3};\n"
        : "+f"(c[0]), "+f"(c[1]), "+f"(c[2]), "+f"(c[3])
        : "r"(a[0]), "r"(a[1]), "r"(a[2]), "r"(a[3]), "r"(b[0]), "r"(b[1]));
}
__device__ __forceinline__ void ldsm_x4(uint32_t* r, uint32_t a) {
    asm volatile("ldmatrix.sync.aligned.m8n8.x4.shared.b16 {%0,%1,%2,%3}, [%4];"
                 : "=r"(r[0]), "=r"(r[1]), "=r"(r[2]), "=r"(r[3]) : "r"(a));
}
__device__ __forceinline__ void ldsm_x4_t(uint32_t* r, uint32_t a) {
    asm volatile("ldmatrix.sync.aligned.m8n8.x4.trans.shared.b16 {%0,%1,%2,%3}, [%4];"
                 : "=r"(r[0]), "=r"(r[1]), "=r"(r[2]), "=r"(r[3]) : "r"(a));
}
__device__ __forceinline__ void cp16(uint32_t dst, const void* src) {
    asm volatile("cp.async.cg.shared.global [%0], [%1], 16;"
                 :: "r"(dst), "l"(src) : "memory");
}
__device__ __forceinline__ void cp16z(uint32_t dst, const void* src, uint32_t sz) {
    asm volatile("cp.async.cg.shared.global [%0], [%1], 16, %2;"
                 :: "r"(dst), "l"(src), "r"(sz) : "memory");
}
__device__ __forceinline__ void cp_commit() {
    asm volatile("cp.async.commit_group;" ::: "memory");
}
__device__ __forceinline__ void cp_wait2() {
    asm volatile("cp.async.wait_group 2;" ::: "memory");
}
__device__ __forceinline__ void cp_wait1() {
    asm volatile("cp.async.wait_group 1;" ::: "memory");
}
__device__ __forceinline__ void cp_wait0() {
    asm volatile("cp.async.wait_group 0;" ::: "memory");
}

// ---------------- small kernels ----------------
__global__ void k_zero() {
    int t = threadIdx.x;
    if (t < NATTR) { g_counts[t] = 0; g_cursors[t] = 0; }
}
__global__ void k_count(const int* __restrict__ attrs) {
    int n = blockIdx.x * blockDim.x + threadIdx.x;
    if (n < NSAMP) atomicAdd(&g_counts[attrs[n]], 1);
}
__global__ void k_scan() {
    if (threadIdx.x == 0) {
        int o = 0, co = 0;
        for (int a = 0; a < NATTR; a++) {
            g_offsets[a] = o;
            g_chunk_off[a] = co;
            o += g_counts[a];
            co += (g_counts[a] + GM2 - 1) / GM2;
        }
        g_chunk_off[NATTR] = co;
    }
}
__global__ void k_scatter(const int* __restrict__ attrs) {
    int n = blockIdx.x * blockDim.x + threadIdx.x;
    if (n < NSAMP) {
        int a = attrs[n];
        int p = atomicAdd(&g_cursors[a], 1);
        g_idx[g_offsets[a] + p] = n;
    }
}

// ---------------- prep kernels ----------------
__global__ void k_prep_img(const float* __restrict__ img) {
    int idx = blockIdx.x * blockDim.x + threadIdx.x;
    if (idx >= M1 * (IMG_DIM / 4)) return;
    int row = idx / (IMG_DIM / 4);
    int c = idx - row * (IMG_DIM / 4);
    int n = row / 3, s = row - 3 * n;
    float4 v = *(const float4*)(img + (size_t)(n * MAX_IN + s) * IMG_DIM + c * 4);
    *(uint2*)(g_af + (size_t)row * IMG_DIM + c * 4) = pack4h(v);
}
__global__ void k_prep_wcnn(const float* __restrict__ W) {
    int idx = blockIdx.x * blockDim.x + threadIdx.x;
    if (idx >= IMG_DIM * FC / 4) return;
    float4 v = *(const float4*)(W + (size_t)idx * 4);
    uint2 hi, lo;
    split4h(v, hi, lo);
    *(uint2*)(g_wh + (size_t)idx * 4) = hi;
    *(uint2*)(g_wl + (size_t)idx * 4) = lo;
}
__global__ void k_prep_w1(const float* __restrict__ W1) {
    int idx = blockIdx.x * blockDim.x + threadIdx.x;
    if (idx >= NATTR * 2 * FC * FC / 4) return;
    float4 v = *(const float4*)(W1 + (size_t)idx * 4);
    uint2 hi, lo;
    split4h(v, hi, lo);
    *(uint2*)(g_w1h + (size_t)idx * 4) = hi;
    *(uint2*)(g_w1l + (size_t)idx * 4) = lo;
}

// ---------------- GEMM1: feats = relu(img3 @ Wcnn + b) ----------------
// 256 thr, 8 warps (4M x 2N of 32x32), 2 CTAs/SM for cross-CTA pipe overlap.
__global__ __launch_bounds__(256) void k_gemm1(const float* __restrict__ bias)
{
    extern __shared__ char smem[];
    const uint32_t sb = (uint32_t)__cvta_generic_to_shared(smem);
    const int tid = threadIdx.x, lane = tid & 31, warp = tid >> 5;
    const int bn0 = blockIdx.x * BN, bm0 = blockIdx.y * BM;
    const int wm = (warp >> 1) * 32, wn = (warp & 1) * 32;
    const int fr = lane >> 2, fc = (lane & 3) * 2;
    const int a_row = lane & 15, a_ks = (lane >> 4) * 8;
    const int b_row = (lane & 7) + ((lane >> 3) & 1) * 8, b_cs = (lane >> 4) * 8;

    // cp.async maps: A 8192B -> 2 cp/thread; B 4096B each -> 1 cp/thread
    const int ar0 = tid >> 2, ac0 = tid & 3;            // chunk tid
    const int ar1 = ar0 + 64;                           // chunk tid+256
    const int brow = tid >> 3, bc2 = tid & 7;
    const __half* sA0 = g_af + (size_t)(bm0 + ar0) * IMG_DIM + ac0 * 8;
    const __half* sA1 = g_af + (size_t)(bm0 + ar1) * IMG_DIM + ac0 * 8;
    const __half* sBh = g_wh + (size_t)brow * FC + bn0 + bc2 * 8;
    const __half* sBl = g_wl + (size_t)brow * FC + bn0 + bc2 * 8;
    const uint32_t dA0 = (uint32_t)(ar0 * (ASTRIDE * 2) + ac0 * 16);
    const uint32_t dA1 = (uint32_t)(ar1 * (ASTRIDE * 2) + ac0 * 16);
    const uint32_t dB  = (uint32_t)(brow * (BSTRIDE * 2) + bc2 * 16);

    float acc[2][4][4];
#pragma unroll
    for (int mt = 0; mt < 2; mt++)
#pragma unroll
        for (int nt = 0; nt < 4; nt++)
#pragma unroll
            for (int i = 0; i < 4; i++) acc[mt][nt][i] = 0.f;

#define G1_ISSUE(t_) do {                                        \
        const uint32_t s_ = sb + ((t_) % NSTG) * STAGE;          \
        const int k0_ = (t_) * BK;                               \
        cp16(s_ + OFF_A + dA0, sA0 + k0_);                       \
        cp16(s_ + OFF_A + dA1, sA1 + k0_);                       \
        cp16(s_ + OFF_BH + dB, sBh + (size_t)k0_ * FC);          \
        cp16(s_ + OFF_BL + dB, sBl + (size_t)k0_ * FC);          \
        cp_commit();                                             \
    } while (0)

    G1_ISSUE(0); G1_ISSUE(1); G1_ISSUE(2);

    for (int t = 0; t < KT1; t++) {
        if (t < KT1 - 2) cp_wait2();
        else if (t == KT1 - 2) cp_wait1();
        else cp_wait0();
        __syncthreads();
        if (t + 3 < KT1) G1_ISSUE(t + 3);

        const uint32_t s = sb + (t % NSTG) * STAGE;
#pragma unroll
        for (int ks = 0; ks < 2; ks++) {
            const int kb = ks * 16;
            uint32_t af[2][4], bfh[2][4], bfl[2][4];
#pragma unroll
            for (int mt = 0; mt < 2; mt++)
                ldsm_x4(af[mt], s + OFF_A
                        + ((wm + mt * 16 + a_row) * ASTRIDE + kb + a_ks) * 2);
#pragma unroll
            for (int np = 0; np < 2; np++) {
                uint32_t rb = s + OFF_BH
                    + ((kb + b_row) * BSTRIDE + wn + np * 16 + b_cs) * 2;
                ldsm_x4_t(bfh[np], rb);
                ldsm_x4_t(bfl[np], rb + (OFF_BL - OFF_BH));
            }
#pragma unroll
            for (int mt = 0; mt < 2; mt++)
#pragma unroll
                for (int nt = 0; nt < 4; nt++)
                    mma16816(acc[mt][nt], af[mt], &bfh[nt >> 1][(nt & 1) * 2]);
#pragma unroll
            for (int mt = 0; mt < 2; mt++)
#pragma unroll
                for (int nt = 0; nt < 4; nt++)
                    mma16816(acc[mt][nt], af[mt], &bfl[nt >> 1][(nt & 1) * 2]);
        }
    }

#pragma unroll
    for (int nt = 0; nt < 4; nt++) {
        int c = bn0 + wn + nt * 8 + fc;
        float b0 = __ldg(bias + c), b1v = __ldg(bias + c + 1);
#pragma unroll
        for (int mt = 0; mt < 2; mt++) {
            int r = bm0 + wm + mt * 16 + fr;
            float2 o;
            o.x = fmaxf(acc[mt][nt][0] + b0, 0.f);
            o.y = fmaxf(acc[mt][nt][1] + b1v, 0.f);
            *(float2*)(g_feats + (size_t)r * FC + c) = o;
            o.x = fmaxf(acc[mt][nt][2] + b0, 0.f);
            o.y = fmaxf(acc[mt][nt][3] + b1v, 0.f);
            *(float2*)(g_feats + (size_t)(r + 8) * FC + c) = o;
        }
    }
#undef G1_ISSUE
}

// ---------------- build x (fp16 single) ----------------
__global__ void k_makex(const int* __restrict__ attrs) {
    int i = blockIdx.x * blockDim.x + threadIdx.x;
    if (i >= NSAMP * FC) return;
    int n = i >> 9;
    int k = i & (FC - 1);
    bool dist = (attrs[n] >= 5);
    float f0 = g_feats[(size_t)(n * 3 + 0) * FC + k];
    float f1 = g_feats[(size_t)(n * 3 + 1) * FC + k];
    float f2 = g_feats[(size_t)(n * 3 + 2) * FC + k];
    float x0 = dist ? f0 * f1 : f0;
    float x1 = dist ? f1 * f2 : f1;
    size_t base = (size_t)n * (2 * FC);
    g_xf[base + k]      = __float2half_rn(x0);
    g_xf[base + FC + k] = __float2half_rn(x1);
}

// ---------------- GEMM2: h = relu(x @ W1[attr] + b1), grouped+gathered -----
__global__ __launch_bounds__(256) void k_gemm2(const float* __restrict__ b1)
{
    const int y = blockIdx.y;
    if (y >= g_chunk_off[NATTR]) return;
    int attr = 0;
#pragma unroll
    for (int a = 0; a < NATTR; a++)
        if (y >= g_chunk_off[a]) attr = a;
    const int chunk = y - g_chunk_off[attr];
    const int cnt = g_counts[attr];
    const int base = g_offsets[attr] + chunk * GM2;
    const int nvalid = min(GM2, cnt - chunk * GM2);

    extern __shared__ char smem[];
    __shared__ int sid[GM2];
    const uint32_t sb = (uint32_t)__cvta_generic_to_shared(smem);
    const int tid = threadIdx.x, lane = tid & 31, warp = tid >> 5;
    const int bn0 = blockIdx.x * BN;
    const int wm = (warp >> 1) * 32, wn = (warp & 1) * 32;
    const int fr = lane >> 2, fc = (lane & 3) * 2;
    const int a_row = lane & 15, a_ks = (lane >> 4) * 8;
    const int b_row = (lane & 7) + ((lane >> 3) & 1) * 8, b_cs = (lane >> 4) * 8;

    if (tid < GM2) sid[tid] = (tid < nvalid) ? g_idx[base + tid] : -1;
    __syncthreads();

    const int ar0 = tid >> 2, ac0 = tid & 3;
    const int ar1 = ar0 + 64;
    const int brow = tid >> 3, bc2 = tid & 7;
    const int s0 = sid[ar0], s1 = sid[ar1];
    const uint32_t asz0 = (s0 >= 0) ? 16u : 0u;
    const uint32_t asz1 = (s1 >= 0) ? 16u : 0u;
    const __half* sA0 = g_xf + (size_t)(s0 < 0 ? 0 : s0) * (2 * FC) + ac0 * 8;
    const __half* sA1 = g_xf + (size_t)(s1 < 0 ? 0 : s1) * (2 * FC) + ac0 * 8;
    const __half* sBh = g_w1h + (size_t)attr * 2 * FC * FC
                        + (size_t)brow * FC + bn0 + bc2 * 8;
    const __half* sBl = g_w1l + (size_t)attr * 2 * FC * FC
                        + (size_t)brow * FC + bn0 + bc2 * 8;
    const uint32_t dA0 = (uint32_t)(ar0 * (ASTRIDE * 2) + ac0 * 16);
    const uint32_t dA1 = (uint32_t)(ar1 * (ASTRIDE * 2) + ac0 * 16);
    const uint32_t dB  = (uint32_t)(brow * (BSTRIDE * 2) + bc2 * 16);

    float acc[2][4][4];
#pragma unroll
    for (int mt = 0; mt < 2; mt++)
#pragma unroll
        for (int nt = 0; nt < 4; nt++)
#pragma unroll
            for (int i = 0; i < 4; i++) acc[mt][nt][i] = 0.f;

#define G2_ISSUE(t_) do {                                        \
        const uint32_t s_ = sb + ((t_) % NSTG) * STAGE;          \
        const int k0_ = (t_) * BK;                               \
        cp16z(s_ + OFF_A + dA0, sA0 + k0_, asz0);                \
        cp16z(s_ + OFF_A + dA1, sA1 + k0_, asz1);                \
        cp16(s_ + OFF_BH + dB, sBh + (size_t)k0_ * FC);          \
        cp16(s_ + OFF_BL + dB, sBl + (size_t)k0_ * FC);          \
        cp_commit();                                             \
    } while (0)

    G2_ISSUE(0); G2_ISSUE(1); G2_ISSUE(2);

    for (int t = 0; t < KT2; t++) {
        if (t < KT2 - 2) cp_wait2();
        else if (t == KT2 - 2) cp_wait1();
        else cp_wait0();
        __syncthreads();
        if (t + 3 < KT2) G2_ISSUE(t + 3);

        const uint32_t s = sb + (t % NSTG) * STAGE;
#pragma unroll
        for (int ks = 0; ks < 2; ks++) {
            const int kb = ks * 16;
            uint32_t af[2][4], bfh[2][4], bfl[2][4];
#pragma unroll
            for (int mt = 0; mt < 2; mt++)
                ldsm_x4(af[mt], s + OFF_A
                        + ((wm + mt * 16 + a_row) * ASTRIDE + kb + a_ks) * 2);
#pragma unroll
            for (int np = 0; np < 2; np++) {
                uint32_t rb = s + OFF_BH
                    + ((kb + b_row) * BSTRIDE + wn + np * 16 + b_cs) * 2;
                ldsm_x4_t(bfh[np], rb);
                ldsm_x4_t(bfl[np], rb + (OFF_BL - OFF_BH));
            }
#pragma unroll
            for (int mt = 0; mt < 2; mt++)
#pragma unroll
                for (int nt = 0; nt < 4; nt++)
                    mma16816(acc[mt][nt], af[mt], &bfh[nt >> 1][(nt & 1) * 2]);
#pragma unroll
            for (int mt = 0; mt < 2; mt++)
#pragma unroll
                for (int nt = 0; nt < 4; nt++)
                    mma16816(acc[mt][nt], af[mt], &bfl[nt >> 1][(nt & 1) * 2]);
        }
    }

#pragma unroll
    for (int nt = 0; nt < 4; nt++) {
        int c = bn0 + wn + nt * 8 + fc;
        float b0 = __ldg(b1 + (size_t)attr * FC + c);
        float b1v = __ldg(b1 + (size_t)attr * FC + c + 1);
#pragma unroll
        for (int mt = 0; mt < 2; mt++) {
            int rA = wm + mt * 16 + fr;
            int sA2 = sid[rA], sB2 = sid[rA + 8];
            if (sA2 >= 0) {
                float2 o;
                o.x = fmaxf(acc[mt][nt][0] + b0, 0.f);
                o.y = fmaxf(acc[mt][nt][1] + b1v, 0.f);
                *(float2*)(g_h + (size_t)sA2 * FC + c) = o;
            }
            if (sB2 >= 0) {
                float2 o;
                o.x = fmaxf(acc[mt][nt][2] + b0, 0.f);
                o.y = fmaxf(acc[mt][nt][3] + b1v, 0.f);
                *(float2*)(g_h + (size_t)sB2 * FC + c) = o;
            }
        }
    }
#undef G2_ISSUE
}

// ---------------- scores = h @ W2[attr] + b2 ----------------
__global__ __launch_bounds__(256) void k_out(
    const int* __restrict__ attrs, const float* __restrict__ W2,
    const float* __restrict__ b2, float* __restrict__ out)
{
    int warp = (blockIdx.x * blockDim.x + threadIdx.x) >> 5;
    int lane = threadIdx.x & 31;
    if (warp >= NSAMP) return;
    int n = warp;
    int a = attrs[n];
    const float* w = W2 + (size_t)a * FC * NANS;
    const float* hp = g_h + (size_t)n * FC;
    float s0 = 0.f, s1 = 0.f;
#pragma unroll
    for (int k = lane; k < FC; k += 32) {
        float hv = hp[k];
        s0 += hv * w[k * 2 + 0];
        s1 += hv * w[k * 2 + 1];
    }
#pragma unroll
    for (int o = 16; o; o >>= 1) {
        s0 += __shfl_down_sync(0xffffffffu, s0, o);
        s1 += __shfl_down_sync(0xffffffffu, s1, o);
    }
    if (lane == 0) {
        out[n * 2 + 0] = s0 + b2[a * 2 + 0];
        out[n * 2 + 1] = s1 + b2[a * 2 + 1];
    }
}

// ---------------- launch ----------------
extern "C" void kernel_launch(void* const* d_in, const int* in_sizes, int n_in,
                              void* d_out, int out_size) {
    const float* img   = (const float*)d_in[0];
    const int*   attrs = (const int*)d_in[1];
    const float* Wcnn  = (const float*)d_in[2];
    const float* bcnn  = (const float*)d_in[3];
    const float* W1    = (const float*)d_in[4];
    const float* b1    = (const float*)d_in[5];
    const float* W2    = (const float*)d_in[6];
    const float* b2    = (const float*)d_in[7];
    float* out = (float*)d_out;

    cudaFuncSetAttribute(k_gemm1, cudaFuncAttributeMaxDynamicSharedMemorySize, SMEM_SZ);
    cudaFuncSetAttribute(k_gemm2, cudaFuncAttributeMaxDynamicSharedMemorySize, SMEM_SZ);

    // prep (slots 1..3), GEMM1 in slot 4 for ncu capture
    k_prep_img<<<(M1 * (IMG_DIM / 4) + 255) / 256, 256>>>(img);
    k_prep_wcnn<<<(IMG_DIM * FC / 4 + 255) / 256, 256>>>(Wcnn);
    k_zero<<<1, 32>>>();

    k_gemm1<<<dim3(FC / BN, M1 / BM), 256, SMEM_SZ>>>(bcnn);

    k_count<<<(NSAMP + 255) / 256, 256>>>(attrs);
    k_scan<<<1, 32>>>();
    k_scatter<<<(NSAMP + 255) / 256, 256>>>(attrs);
    k_prep_w1<<<(NATTR * 2 * FC * FC / 4 + 255) / 256, 256>>>(W1);
    k_makex<<<(NSAMP * FC + 255) / 256, 256>>>(attrs);

    k_gemm2<<<dim3(FC / BN, MAXCH), 256, SMEM_SZ>>>(b1);

    k_out<<<NSAMP / 8, 256>>>(attrs, W2, b2, out);
}

// round 9
// speedup vs baseline: 2.2527x; 1.1295x over previous
#include <cuda_runtime.h>
#include <cuda_fp16.h>
#include <stdint.h>

#define NSAMP 8192
#define MAX_IN 8
#define IMG_DIM 3200
#define FC 512
#define NATTR 7
#define NANS 2
#define M1 (NSAMP * 3)

// GEMM tiling: 128x128 block, BK=32, 256 thr (8 warps = 2M x 4N of 64x32)
#define BM 128
#define BN 128
#define BK 32
#define KT1 (IMG_DIM / BK)         // 100
#define KT2 ((2 * FC) / BK)        // 32
#define NSTG 3
#define ASTRIDE 40                 // fp16 elems per A smem row (80 B)
#define BSTRIDE 136                // fp16 elems per B smem row (272 B)
#define OFF_A  0                   // A: 128 * 80 = 10240 B
#define OFF_BH 10240               // B: 32 * 272 = 8704 B each
#define OFF_BL 18944
#define STAGE  27648
#define SMEM_SZ (NSTG * STAGE)     // 82944 -> 2 CTAs/SM
#define GM2 128
#define MAXCH (NSAMP / GM2 + NATTR)  // 71

// ---------------- scratch (static device globals) ----------------
__device__ __align__(16) __half g_af[(size_t)M1 * IMG_DIM];
__device__ __align__(16) __half g_wh[(size_t)IMG_DIM * FC];
__device__ __align__(16) __half g_wl[(size_t)IMG_DIM * FC];
__device__ __align__(16) __half g_w1h[(size_t)NATTR * 2 * FC * FC];
__device__ __align__(16) __half g_w1l[(size_t)NATTR * 2 * FC * FC];
__device__ __align__(16) __half g_xf[(size_t)NSAMP * 2 * FC];
__device__ __align__(16) float g_feats[(size_t)M1 * FC];
__device__ __align__(16) float g_h[(size_t)NSAMP * FC];
__device__ int g_counts[NATTR];
__device__ int g_offsets[NATTR];
__device__ int g_cursors[NATTR];
__device__ int g_chunk_off[NATTR + 1];
__device__ int g_idx[NSAMP];

// ---------------- helpers ----------------
__device__ __forceinline__ uint2 pack4h(float4 v) {
    __half2 a = __floats2half2_rn(v.x, v.y);
    __half2 b = __floats2half2_rn(v.z, v.w);
    uint2 r;
    r.x = *(uint32_t*)&a;
    r.y = *(uint32_t*)&b;
    return r;
}
__device__ __forceinline__ void split4h(float4 v, uint2& hi, uint2& lo) {
    __half2 h01 = __floats2half2_rn(v.x, v.y);
    __half2 h23 = __floats2half2_rn(v.z, v.w);
    float2 f01 = __half22float2(h01);
    float2 f23 = __half22float2(h23);
    __half2 l01 = __floats2half2_rn(v.x - f01.x, v.y - f01.y);
    __half2 l23 = __floats2half2_rn(v.z - f23.x, v.w - f23.y);
    hi.x = *(uint32_t*)&h01; hi.y = *(uint32_t*)&h23;
    lo.x = *(uint32_t*)&l01; lo.y = *(uint32_t*)&l23;
}
__device__ __forceinline__ void mma16816(float* c, const uint32_t* a, const uint32_t* b) {
    asm("mma.sync.aligned.m16n8k16.row.col.f32.f16.f16.f32 "
        "{%0,%1,%2,%3}, {%4,%5,%6,%7}, {%8,%9}, {%0,%1,%2,%3};\n"
        : "+f"(c[0]), "+f"(c[1]), "+f"(c[2]), "+f"(c[3])
        : "r"(a[0]), "r"(a[1]), "r"(a[2]), "r"(a[3]), "r"(b[0]), "r"(b[1]));
}
__device__ __forceinline__ void ldsm_x4(uint32_t* r, uint32_t a) {
    asm volatile("ldmatrix.sync.aligned.m8n8.x4.shared.b16 {%0,%1,%2,%3}, [%4];"
                 : "=r"(r[0]), "=r"(r[1]), "=r"(r[2]), "=r"(r[3]) : "r"(a));
}
__device__ __forceinline__ void ldsm_x4_t(uint32_t* r, uint32_t a) {
    asm volatile("ldmatrix.sync.aligned.m8n8.x4.trans.shared.b16 {%0,%1,%2,%3}, [%4];"
                 : "=r"(r[0]), "=r"(r[1]), "=r"(r[2]), "=r"(r[3]) : "r"(a));
}
__device__ __forceinline__ void cp16(uint32_t dst, const void* src) {
    asm volatile("cp.async.cg.shared.global [%0], [%1], 16;"
                 :: "r"(dst), "l"(src) : "memory");
}
__device__ __forceinline__ void cp16z(uint32_t dst, const void* src, uint32_t sz) {
    asm volatile("cp.async.cg.shared.global [%0], [%1], 16, %2;"
                 :: "r"(dst), "l"(src), "r"(sz) : "memory");
}
__device__ __forceinline__ void cp_commit() {
    asm volatile("cp.async.commit_group;" ::: "memory");
}
__device__ __forceinline__ void cp_wait1() {
    asm volatile("cp.async.wait_group 1;" ::: "memory");
}
__device__ __forceinline__ void cp_wait0() {
    asm volatile("cp.async.wait_group 0;" ::: "memory");
}

// ---------------- small kernels ----------------
__global__ void k_zero() {
    int t = threadIdx.x;
    if (t < NATTR) { g_counts[t] = 0; g_cursors[t] = 0; }
}
__global__ void k_count(const int* __restrict__ attrs) {
    int n = blockIdx.x * blockDim.x + threadIdx.x;
    if (n < NSAMP) atomicAdd(&g_counts[attrs[n]], 1);
}
__global__ void k_scan() {
    if (threadIdx.x == 0) {
        int o = 0, co = 0;
        for (int a = 0; a < NATTR; a++) {
            g_offsets[a] = o;
            g_chunk_off[a] = co;
            o += g_counts[a];
            co += (g_counts[a] + GM2 - 1) / GM2;
        }
        g_chunk_off[NATTR] = co;
    }
}
__global__ void k_scatter(const int* __restrict__ attrs) {
    int n = blockIdx.x * blockDim.x + threadIdx.x;
    if (n < NSAMP) {
        int a = attrs[n];
        int p = atomicAdd(&g_cursors[a], 1);
        g_idx[g_offsets[a] + p] = n;
    }
}

// ---------------- prep kernels ----------------
__global__ void k_prep_img(const float* __restrict__ img) {
    int idx = blockIdx.x * blockDim.x + threadIdx.x;
    if (idx >= M1 * (IMG_DIM / 4)) return;
    int row = idx / (IMG_DIM / 4);
    int c = idx - row * (IMG_DIM / 4);
    int n = row / 3, s = row - 3 * n;
    float4 v = *(const float4*)(img + (size_t)(n * MAX_IN + s) * IMG_DIM + c * 4);
    *(uint2*)(g_af + (size_t)row * IMG_DIM + c * 4) = pack4h(v);
}
__global__ void k_prep_wcnn(const float* __restrict__ W) {
    int idx = blockIdx.x * blockDim.x + threadIdx.x;
    if (idx >= IMG_DIM * FC / 4) return;
    float4 v = *(const float4*)(W + (size_t)idx * 4);
    uint2 hi, lo;
    split4h(v, hi, lo);
    *(uint2*)(g_wh + (size_t)idx * 4) = hi;
    *(uint2*)(g_wl + (size_t)idx * 4) = lo;
}
__global__ void k_prep_w1(const float* __restrict__ W1) {
    int idx = blockIdx.x * blockDim.x + threadIdx.x;
    if (idx >= NATTR * 2 * FC * FC / 4) return;
    float4 v = *(const float4*)(W1 + (size_t)idx * 4);
    uint2 hi, lo;
    split4h(v, hi, lo);
    *(uint2*)(g_w1h + (size_t)idx * 4) = hi;
    *(uint2*)(g_w1l + (size_t)idx * 4) = lo;
}

// ---------------- GEMM1: feats = relu(img3 @ Wcnn + b) ----------------
// 256 thr, 8 warps (2M x 4N of 64x32), 2 CTAs/SM, 128 B LDSM per MMA.
__global__ __launch_bounds__(256, 2) void k_gemm1(const float* __restrict__ bias)
{
    extern __shared__ char smem[];
    const uint32_t sb = (uint32_t)__cvta_generic_to_shared(smem);
    const int tid = threadIdx.x, lane = tid & 31, warp = tid >> 5;
    const int bn0 = blockIdx.x * BN, bm0 = blockIdx.y * BM;
    const int wm = (warp >> 2) * 64, wn = (warp & 3) * 32;
    const int fr = lane >> 2, fc = (lane & 3) * 2;
    const int a_row = lane & 15, a_ks = (lane >> 4) * 8;
    const int b_row = (lane & 7) + ((lane >> 3) & 1) * 8, b_cs = (lane >> 4) * 8;

    // cp.async maps: A 8192B -> 2/thr; B hi 8192B -> 2/thr; B lo -> 2/thr
    const int ar0 = tid >> 2, ac0 = tid & 3;
    const int brow = tid >> 4, bc2 = tid & 15;
    const __half* sA0 = g_af + (size_t)(bm0 + ar0) * IMG_DIM + ac0 * 8;
    const __half* sA1 = g_af + (size_t)(bm0 + ar0 + 64) * IMG_DIM + ac0 * 8;
    const __half* sBh = g_wh + (size_t)brow * FC + bn0 + bc2 * 8;
    const __half* sBl = g_wl + (size_t)brow * FC + bn0 + bc2 * 8;
    const uint32_t dA0 = (uint32_t)(ar0 * (ASTRIDE * 2) + ac0 * 16);
    const uint32_t dA1 = dA0 + 64 * (ASTRIDE * 2);
    const uint32_t dB0 = (uint32_t)(brow * (BSTRIDE * 2) + bc2 * 16);
    const uint32_t dB1 = dB0 + 16 * (BSTRIDE * 2);

    float acc[4][4][4];
#pragma unroll
    for (int mt = 0; mt < 4; mt++)
#pragma unroll
        for (int nt = 0; nt < 4; nt++)
#pragma unroll
            for (int i = 0; i < 4; i++) acc[mt][nt][i] = 0.f;

#define G1_ISSUE(t_) do {                                            \
        const uint32_t s_ = sb + ((t_) % NSTG) * STAGE;              \
        const int k0_ = (t_) * BK;                                   \
        cp16(s_ + OFF_A + dA0, sA0 + k0_);                           \
        cp16(s_ + OFF_A + dA1, sA1 + k0_);                           \
        cp16(s_ + OFF_BH + dB0, sBh + (size_t)k0_ * FC);             \
        cp16(s_ + OFF_BH + dB1, sBh + (size_t)(k0_ + 16) * FC);      \
        cp16(s_ + OFF_BL + dB0, sBl + (size_t)k0_ * FC);             \
        cp16(s_ + OFF_BL + dB1, sBl + (size_t)(k0_ + 16) * FC);      \
        cp_commit();                                                 \
    } while (0)

    G1_ISSUE(0); G1_ISSUE(1);

    for (int t = 0; t < KT1; t++) {
        if (t < KT1 - 1) cp_wait1(); else cp_wait0();
        __syncthreads();
        if (t + 2 < KT1) G1_ISSUE(t + 2);

        const uint32_t s = sb + (t % NSTG) * STAGE;
#pragma unroll
        for (int ks = 0; ks < 2; ks++) {
            const int kb = ks * 16;
            uint32_t af[4][4], bfh[2][4], bfl[2][4];
#pragma unroll
            for (int mt = 0; mt < 4; mt++)
                ldsm_x4(af[mt], s + OFF_A
                        + ((wm + mt * 16 + a_row) * ASTRIDE + kb + a_ks) * 2);
#pragma unroll
            for (int np = 0; np < 2; np++) {
                uint32_t rb = s + OFF_BH
                    + ((kb + b_row) * BSTRIDE + wn + np * 16 + b_cs) * 2;
                ldsm_x4_t(bfh[np], rb);
                ldsm_x4_t(bfl[np], rb + (OFF_BL - OFF_BH));
            }
            // term-major: 16 independent MMAs per term
#pragma unroll
            for (int mt = 0; mt < 4; mt++)
#pragma unroll
                for (int nt = 0; nt < 4; nt++)
                    mma16816(acc[mt][nt], af[mt], &bfh[nt >> 1][(nt & 1) * 2]);
#pragma unroll
            for (int mt = 0; mt < 4; mt++)
#pragma unroll
                for (int nt = 0; nt < 4; nt++)
                    mma16816(acc[mt][nt], af[mt], &bfl[nt >> 1][(nt & 1) * 2]);
        }
    }

#pragma unroll
    for (int nt = 0; nt < 4; nt++) {
        int c = bn0 + wn + nt * 8 + fc;
        float b0 = __ldg(bias + c), b1v = __ldg(bias + c + 1);
#pragma unroll
        for (int mt = 0; mt < 4; mt++) {
            int r = bm0 + wm + mt * 16 + fr;
            float2 o;
            o.x = fmaxf(acc[mt][nt][0] + b0, 0.f);
            o.y = fmaxf(acc[mt][nt][1] + b1v, 0.f);
            *(float2*)(g_feats + (size_t)r * FC + c) = o;
            o.x = fmaxf(acc[mt][nt][2] + b0, 0.f);
            o.y = fmaxf(acc[mt][nt][3] + b1v, 0.f);
            *(float2*)(g_feats + (size_t)(r + 8) * FC + c) = o;
        }
    }
#undef G1_ISSUE
}

// ---------------- build x (fp16 single) ----------------
__global__ void k_makex(const int* __restrict__ attrs) {
    int i = blockIdx.x * blockDim.x + threadIdx.x;
    if (i >= NSAMP * FC) return;
    int n = i >> 9;
    int k = i & (FC - 1);
    bool dist = (attrs[n] >= 5);
    float f0 = g_feats[(size_t)(n * 3 + 0) * FC + k];
    float f1 = g_feats[(size_t)(n * 3 + 1) * FC + k];
    float f2 = g_feats[(size_t)(n * 3 + 2) * FC + k];
    float x0 = dist ? f0 * f1 : f0;
    float x1 = dist ? f1 * f2 : f1;
    size_t base = (size_t)n * (2 * FC);
    g_xf[base + k]      = __float2half_rn(x0);
    g_xf[base + FC + k] = __float2half_rn(x1);
}

// ---------------- GEMM2: h = relu(x @ W1[attr] + b1), grouped+gathered -----
__global__ __launch_bounds__(256, 2) void k_gemm2(const float* __restrict__ b1)
{
    const int y = blockIdx.y;
    if (y >= g_chunk_off[NATTR]) return;
    int attr = 0;
#pragma unroll
    for (int a = 0; a < NATTR; a++)
        if (y >= g_chunk_off[a]) attr = a;
    const int chunk = y - g_chunk_off[attr];
    const int cnt = g_counts[attr];
    const int base = g_offsets[attr] + chunk * GM2;
    const int nvalid = min(GM2, cnt - chunk * GM2);

    extern __shared__ char smem[];
    __shared__ int sid[GM2];
    const uint32_t sb = (uint32_t)__cvta_generic_to_shared(smem);
    const int tid = threadIdx.x, lane = tid & 31, warp = tid >> 5;
    const int bn0 = blockIdx.x * BN;
    const int wm = (warp >> 2) * 64, wn = (warp & 3) * 32;
    const int fr = lane >> 2, fc = (lane & 3) * 2;
    const int a_row = lane & 15, a_ks = (lane >> 4) * 8;
    const int b_row = (lane & 7) + ((lane >> 3) & 1) * 8, b_cs = (lane >> 4) * 8;

    if (tid < GM2) sid[tid] = (tid < nvalid) ? g_idx[base + tid] : -1;
    __syncthreads();

    const int ar0 = tid >> 2, ac0 = tid & 3;
    const int brow = tid >> 4, bc2 = tid & 15;
    const int s0 = sid[ar0], s1 = sid[ar0 + 64];
    const uint32_t asz0 = (s0 >= 0) ? 16u : 0u;
    const uint32_t asz1 = (s1 >= 0) ? 16u : 0u;
    const __half* sA0 = g_xf + (size_t)(s0 < 0 ? 0 : s0) * (2 * FC) + ac0 * 8;
    const __half* sA1 = g_xf + (size_t)(s1 < 0 ? 0 : s1) * (2 * FC) + ac0 * 8;
    const __half* sBh = g_w1h + (size_t)attr * 2 * FC * FC
                        + (size_t)brow * FC + bn0 + bc2 * 8;
    const __half* sBl = g_w1l + (size_t)attr * 2 * FC * FC
                        + (size_t)brow * FC + bn0 + bc2 * 8;
    const uint32_t dA0 = (uint32_t)(ar0 * (ASTRIDE * 2) + ac0 * 16);
    const uint32_t dA1 = dA0 + 64 * (ASTRIDE * 2);
    const uint32_t dB0 = (uint32_t)(brow * (BSTRIDE * 2) + bc2 * 16);
    const uint32_t dB1 = dB0 + 16 * (BSTRIDE * 2);

    float acc[4][4][4];
#pragma unroll
    for (int mt = 0; mt < 4; mt++)
#pragma unroll
        for (int nt = 0; nt < 4; nt++)
#pragma unroll
            for (int i = 0; i < 4; i++) acc[mt][nt][i] = 0.f;

#define G2_ISSUE(t_) do {                                            \
        const uint32_t s_ = sb + ((t_) % NSTG) * STAGE;              \
        const int k0_ = (t_) * BK;                                   \
        cp16z(s_ + OFF_A + dA0, sA0 + k0_, asz0);                    \
        cp16z(s_ + OFF_A + dA1, sA1 + k0_, asz1);                    \
        cp16(s_ + OFF_BH + dB0, sBh + (size_t)k0_ * FC);             \
        cp16(s_ + OFF_BH + dB1, sBh + (size_t)(k0_ + 16) * FC);     \
        cp16(s_ + OFF_BL + dB0, sBl + (size_t)k0_ * FC);             \
        cp16(s_ + OFF_BL + dB1, sBl + (size_t)(k0_ + 16) * FC);     \
        cp_commit();                                                 \
    } while (0)

    G2_ISSUE(0); G2_ISSUE(1);

    for (int t = 0; t < KT2; t++) {
        if (t < KT2 - 1) cp_wait1(); else cp_wait0();
        __syncthreads();
        if (t + 2 < KT2) G2_ISSUE(t + 2);

        const uint32_t s = sb + (t % NSTG) * STAGE;
#pragma unroll
        for (int ks = 0; ks < 2; ks++) {
            const int kb = ks * 16;
            uint32_t af[4][4], bfh[2][4], bfl[2][4];
#pragma unroll
            for (int mt = 0; mt < 4; mt++)
                ldsm_x4(af[mt], s + OFF_A
                        + ((wm + mt * 16 + a_row) * ASTRIDE + kb + a_ks) * 2);
#pragma unroll
            for (int np = 0; np < 2; np++) {
                uint32_t rb = s + OFF_BH
                    + ((kb + b_row) * BSTRIDE + wn + np * 16 + b_cs) * 2;
                ldsm_x4_t(bfh[np], rb);
                ldsm_x4_t(bfl[np], rb + (OFF_BL - OFF_BH));
            }
#pragma unroll
            for (int mt = 0; mt < 4; mt++)
#pragma unroll
                for (int nt = 0; nt < 4; nt++)
                    mma16816(acc[mt][nt], af[mt], &bfh[nt >> 1][(nt & 1) * 2]);
#pragma unroll
            for (int mt = 0; mt < 4; mt++)
#pragma unroll
                for (int nt = 0; nt < 4; nt++)
                    mma16816(acc[mt][nt], af[mt], &bfl[nt >> 1][(nt & 1) * 2]);
        }
    }

#pragma unroll
    for (int nt = 0; nt < 4; nt++) {
        int c = bn0 + wn + nt * 8 + fc;
        float b0 = __ldg(b1 + (size_t)attr * FC + c);
        float b1v = __ldg(b1 + (size_t)attr * FC + c + 1);
#pragma unroll
        for (int mt = 0; mt < 4; mt++) {
            int rA = wm + mt * 16 + fr;
            int sA2 = sid[rA], sB2 = sid[rA + 8];
            if (sA2 >= 0) {
                float2 o;
                o.x = fmaxf(acc[mt][nt][0] + b0, 0.f);
                o.y = fmaxf(acc[mt][nt][1] + b1v, 0.f);
                *(float2*)(g_h + (size_t)sA2 * FC + c) = o;
            }
            if (sB2 >= 0) {
                float2 o;
                o.x = fmaxf(acc[mt][nt][2] + b0, 0.f);
                o.y = fmaxf(acc[mt][nt][3] + b1v, 0.f);
                *(float2*)(g_h + (size_t)sB2 * FC + c) = o;
            }
        }
    }
#undef G2_ISSUE
}

// ---------------- scores = h @ W2[attr] + b2 ----------------
__global__ __launch_bounds__(256) void k_out(
    const int* __restrict__ attrs, const float* __restrict__ W2,
    const float* __restrict__ b2, float* __restrict__ out)
{
    int warp = (blockIdx.x * blockDim.x + threadIdx.x) >> 5;
    int lane = threadIdx.x & 31;
    if (warp >= NSAMP) return;
    int n = warp;
    int a = attrs[n];
    const float* w = W2 + (size_t)a * FC * NANS;
    const float* hp = g_h + (size_t)n * FC;
    float s0 = 0.f, s1 = 0.f;
#pragma unroll
    for (int k = lane; k < FC; k += 32) {
        float hv = hp[k];
        s0 += hv * w[k * 2 + 0];
        s1 += hv * w[k * 2 + 1];
    }
#pragma unroll
    for (int o = 16; o; o >>= 1) {
        s0 += __shfl_down_sync(0xffffffffu, s0, o);
        s1 += __shfl_down_sync(0xffffffffu, s1, o);
    }
    if (lane == 0) {
        out[n * 2 + 0] = s0 + b2[a * 2 + 0];
        out[n * 2 + 1] = s1 + b2[a * 2 + 1];
    }
}

// ---------------- launch ----------------
extern "C" void kernel_launch(void* const* d_in, const int* in_sizes, int n_in,
                              void* d_out, int out_size) {
    const float* img   = (const float*)d_in[0];
    const int*   attrs = (const int*)d_in[1];
    const float* Wcnn  = (const float*)d_in[2];
    const float* bcnn  = (const float*)d_in[3];
    const float* W1    = (const float*)d_in[4];
    const float* b1    = (const float*)d_in[5];
    const float* W2    = (const float*)d_in[6];
    const float* b2    = (const float*)d_in[7];
    float* out = (float*)d_out;

    cudaFuncSetAttribute(k_gemm1, cudaFuncAttributeMaxDynamicSharedMemorySize, SMEM_SZ);
    cudaFuncSetAttribute(k_gemm2, cudaFuncAttributeMaxDynamicSharedMemorySize, SMEM_SZ);

    // prep (slots 1..3), GEMM1 in slot 4 for ncu capture
    k_prep_img<<<(M1 * (IMG_DIM / 4) + 255) / 256, 256>>>(img);
    k_prep_wcnn<<<(IMG_DIM * FC / 4 + 255) / 256, 256>>>(Wcnn);
    k_zero<<<1, 32>>>();

    k_gemm1<<<dim3(FC / BN, M1 / BM), 256, SMEM_SZ>>>(bcnn);

    k_count<<<(NSAMP + 255) / 256, 256>>>(attrs);
    k_scan<<<1, 32>>>();
    k_scatter<<<(NSAMP + 255) / 256, 256>>>(attrs);
    k_prep_w1<<<(NATTR * 2 * FC * FC / 4 + 255) / 256, 256>>>(W1);
    k_makex<<<(NSAMP * FC + 255) / 256, 256>>>(attrs);

    k_gemm2<<<dim3(FC / BN, MAXCH), 256, SMEM_SZ>>>(b1);

    k_out<<<NSAMP / 8, 256>>>(attrs, W2, b2, out);
}

// round 10
// speedup vs baseline: 3.1875x; 1.4150x over previous
#include <cuda_runtime.h>
#include <cuda_fp16.h>
#include <stdint.h>

#define NSAMP 8192
#define MAX_IN 8
#define IMG_DIM 3200
#define FC 512
#define NATTR 7
#define NANS 2
#define M1 (NSAMP * 3)

// Common tiling: 128x128 block, BK=32, 256 thr (8 warps = 2M x 4N of 64x32)
#define BM 128
#define BN 128
#define BK 32
#define KT1 (IMG_DIM / BK)         // 100
#define KT2 ((2 * FC) / BK)        // 32
#define ASTRIDE 40                 // fp16 elems per A smem row (80 B)
#define BSTRIDE 136                // fp16 elems per B smem row (272 B)

// GEMM1 (single-term B): stage = A(10240) + B(8704)
#define OFF1_A  0
#define OFF1_B  10240
#define STAGE1  18944
#define NSTG1   4
#define SMEM1   (NSTG1 * STAGE1)   // 75776 -> 2 CTAs/SM

// GEMM2 (two-term B): stage = A(10240) + Bh(8704) + Bl(8704)
#define OFF2_A  0
#define OFF2_BH 10240
#define OFF2_BL 18944
#define STAGE2  27648
#define NSTG2   3
#define SMEM2   (NSTG2 * STAGE2)   // 82944 -> 2 CTAs/SM

#define GM2 128
#define MAXCH (NSAMP / GM2 + NATTR)  // 71

// ---------------- scratch (static device globals) ----------------
__device__ __align__(16) __half g_af[(size_t)M1 * IMG_DIM];
__device__ __align__(16) __half g_wh[(size_t)IMG_DIM * FC];
__device__ __align__(16) __half g_w1h[(size_t)NATTR * 2 * FC * FC];
__device__ __align__(16) __half g_w1l[(size_t)NATTR * 2 * FC * FC];
__device__ __align__(16) __half g_xf[(size_t)NSAMP * 2 * FC];
__device__ __align__(16) float g_feats[(size_t)M1 * FC];
__device__ __align__(16) float g_h[(size_t)NSAMP * FC];
__device__ int g_counts[NATTR];
__device__ int g_offsets[NATTR];
__device__ int g_cursors[NATTR];
__device__ int g_chunk_off[NATTR + 1];
__device__ int g_idx[NSAMP];

// ---------------- helpers ----------------
__device__ __forceinline__ uint2 pack4h(float4 v) {
    __half2 a = __floats2half2_rn(v.x, v.y);
    __half2 b = __floats2half2_rn(v.z, v.w);
    uint2 r;
    r.x = *(uint32_t*)&a;
    r.y = *(uint32_t*)&b;
    return r;
}
__device__ __forceinline__ void split4h(float4 v, uint2& hi, uint2& lo) {
    __half2 h01 = __floats2half2_rn(v.x, v.y);
    __half2 h23 = __floats2half2_rn(v.z, v.w);
    float2 f01 = __half22float2(h01);
    float2 f23 = __half22float2(h23);
    __half2 l01 = __floats2half2_rn(v.x - f01.x, v.y - f01.y);
    __half2 l23 = __floats2half2_rn(v.z - f23.x, v.w - f23.y);
    hi.x = *(uint32_t*)&h01; hi.y = *(uint32_t*)&h23;
    lo.x = *(uint32_t*)&l01; lo.y = *(uint32_t*)&l23;
}
__device__ __forceinline__ void mma16816(float* c, const uint32_t* a, const uint32_t* b) {
    asm("mma.sync.aligned.m16n8k16.row.col.f32.f16.f16.f32 "
        "{%0,%1,%2,%3}, {%4,%5,%6,%7}, {%8,%9}, {%0,%1,%2,%3};\n"
        : "+f"(c[0]), "+f"(c[1]), "+f"(c[2]), "+f"(c[3])
        : "r"(a[0]), "r"(a[1]), "r"(a[2]), "r"(a[3]), "r"(b[0]), "r"(b[1]));
}
__device__ __forceinline__ void ldsm_x4(uint32_t* r, uint32_t a) {
    asm volatile("ldmatrix.sync.aligned.m8n8.x4.shared.b16 {%0,%1,%2,%3}, [%4];"
                 : "=r"(r[0]), "=r"(r[1]), "=r"(r[2]), "=r"(r[3]) : "r"(a));
}
__device__ __forceinline__ void ldsm_x4_t(uint32_t* r, uint32_t a) {
    asm volatile("ldmatrix.sync.aligned.m8n8.x4.trans.shared.b16 {%0,%1,%2,%3}, [%4];"
                 : "=r"(r[0]), "=r"(r[1]), "=r"(r[2]), "=r"(r[3]) : "r"(a));
}
__device__ __forceinline__ void cp16(uint32_t dst, const void* src) {
    asm volatile("cp.async.cg.shared.global [%0], [%1], 16;"
                 :: "r"(dst), "l"(src) : "memory");
}
__device__ __forceinline__ void cp16z(uint32_t dst, const void* src, uint32_t sz) {
    asm volatile("cp.async.cg.shared.global [%0], [%1], 16, %2;"
                 :: "r"(dst), "l"(src), "r"(sz) : "memory");
}
__device__ __forceinline__ void cp_commit() {
    asm volatile("cp.async.commit_group;" ::: "memory");
}
__device__ __forceinline__ void cp_wait2() {
    asm volatile("cp.async.wait_group 2;" ::: "memory");
}
__device__ __forceinline__ void cp_wait1() {
    asm volatile("cp.async.wait_group 1;" ::: "memory");
}
__device__ __forceinline__ void cp_wait0() {
    asm volatile("cp.async.wait_group 0;" ::: "memory");
}

// ---------------- small kernels ----------------
__global__ void k_zero() {
    int t = threadIdx.x;
    if (t < NATTR) { g_counts[t] = 0; g_cursors[t] = 0; }
}
__global__ void k_count(const int* __restrict__ attrs) {
    int n = blockIdx.x * blockDim.x + threadIdx.x;
    if (n < NSAMP) atomicAdd(&g_counts[attrs[n]], 1);
}
__global__ void k_scan() {
    if (threadIdx.x == 0) {
        int o = 0, co = 0;
        for (int a = 0; a < NATTR; a++) {
            g_offsets[a] = o;
            g_chunk_off[a] = co;
            o += g_counts[a];
            co += (g_counts[a] + GM2 - 1) / GM2;
        }
        g_chunk_off[NATTR] = co;
    }
}
__global__ void k_scatter(const int* __restrict__ attrs) {
    int n = blockIdx.x * blockDim.x + threadIdx.x;
    if (n < NSAMP) {
        int a = attrs[n];
        int p = atomicAdd(&g_cursors[a], 1);
        g_idx[g_offsets[a] + p] = n;
    }
}

// ---------------- prep kernels ----------------
__global__ void k_prep_img(const float* __restrict__ img) {
    int idx = blockIdx.x * blockDim.x + threadIdx.x;
    if (idx >= M1 * (IMG_DIM / 4)) return;
    int row = idx / (IMG_DIM / 4);
    int c = idx - row * (IMG_DIM / 4);
    int n = row / 3, s = row - 3 * n;
    float4 v = *(const float4*)(img + (size_t)(n * MAX_IN + s) * IMG_DIM + c * 4);
    *(uint2*)(g_af + (size_t)row * IMG_DIM + c * 4) = pack4h(v);
}
__global__ void k_prep_wcnn(const float* __restrict__ W) {
    int idx = blockIdx.x * blockDim.x + threadIdx.x;
    if (idx >= IMG_DIM * FC / 4) return;
    float4 v = *(const float4*)(W + (size_t)idx * 4);
    *(uint2*)(g_wh + (size_t)idx * 4) = pack4h(v);
}
__global__ void k_prep_w1(const float* __restrict__ W1) {
    int idx = blockIdx.x * blockDim.x + threadIdx.x;
    if (idx >= NATTR * 2 * FC * FC / 4) return;
    float4 v = *(const float4*)(W1 + (size_t)idx * 4);
    uint2 hi, lo;
    split4h(v, hi, lo);
    *(uint2*)(g_w1h + (size_t)idx * 4) = hi;
    *(uint2*)(g_w1l + (size_t)idx * 4) = lo;
}

// ---------------- GEMM1: feats = relu(img3 @ Wcnn + b), single-term fp16 ----
__global__ __launch_bounds__(256, 2) void k_gemm1(const float* __restrict__ bias)
{
    extern __shared__ char smem[];
    const uint32_t sb = (uint32_t)__cvta_generic_to_shared(smem);
    const int tid = threadIdx.x, lane = tid & 31, warp = tid >> 5;
    const int bn0 = blockIdx.x * BN, bm0 = blockIdx.y * BM;
    const int wm = (warp >> 2) * 64, wn = (warp & 3) * 32;
    const int fr = lane >> 2, fc = (lane & 3) * 2;
    const int a_row = lane & 15, a_ks = (lane >> 4) * 8;
    const int b_row = (lane & 7) + ((lane >> 3) & 1) * 8, b_cs = (lane >> 4) * 8;

    // cp.async maps: A 8192B -> 2/thr; B 8192B -> 2/thr
    const int ar0 = tid >> 2, ac0 = tid & 3;
    const int brow = tid >> 4, bc2 = tid & 15;
    const __half* sA0 = g_af + (size_t)(bm0 + ar0) * IMG_DIM + ac0 * 8;
    const __half* sA1 = g_af + (size_t)(bm0 + ar0 + 64) * IMG_DIM + ac0 * 8;
    const __half* sB  = g_wh + (size_t)brow * FC + bn0 + bc2 * 8;
    const uint32_t dA0 = (uint32_t)(ar0 * (ASTRIDE * 2) + ac0 * 16);
    const uint32_t dA1 = dA0 + 64 * (ASTRIDE * 2);
    const uint32_t dB0 = (uint32_t)(brow * (BSTRIDE * 2) + bc2 * 16);
    const uint32_t dB1 = dB0 + 16 * (BSTRIDE * 2);

    float acc[4][4][4];
#pragma unroll
    for (int mt = 0; mt < 4; mt++)
#pragma unroll
        for (int nt = 0; nt < 4; nt++)
#pragma unroll
            for (int i = 0; i < 4; i++) acc[mt][nt][i] = 0.f;

#define G1_ISSUE(t_) do {                                            \
        const uint32_t s_ = sb + ((t_) % NSTG1) * STAGE1;            \
        const int k0_ = (t_) * BK;                                   \
        cp16(s_ + OFF1_A + dA0, sA0 + k0_);                          \
        cp16(s_ + OFF1_A + dA1, sA1 + k0_);                          \
        cp16(s_ + OFF1_B + dB0, sB + (size_t)k0_ * FC);              \
        cp16(s_ + OFF1_B + dB1, sB + (size_t)(k0_ + 16) * FC);       \
        cp_commit();                                                 \
    } while (0)

    G1_ISSUE(0); G1_ISSUE(1); G1_ISSUE(2);

    for (int t = 0; t < KT1; t++) {
        if (t < KT1 - 2) cp_wait2();
        else if (t == KT1 - 2) cp_wait1();
        else cp_wait0();
        __syncthreads();
        if (t + 3 < KT1) G1_ISSUE(t + 3);

        const uint32_t s = sb + (t % NSTG1) * STAGE1;
#pragma unroll
        for (int ks = 0; ks < 2; ks++) {
            const int kb = ks * 16;
            uint32_t af[4][4], bf[2][4];
#pragma unroll
            for (int mt = 0; mt < 4; mt++)
                ldsm_x4(af[mt], s + OFF1_A
                        + ((wm + mt * 16 + a_row) * ASTRIDE + kb + a_ks) * 2);
#pragma unroll
            for (int np = 0; np < 2; np++)
                ldsm_x4_t(bf[np], s + OFF1_B
                          + ((kb + b_row) * BSTRIDE + wn + np * 16 + b_cs) * 2);
#pragma unroll
            for (int mt = 0; mt < 4; mt++)
#pragma unroll
                for (int nt = 0; nt < 4; nt++)
                    mma16816(acc[mt][nt], af[mt], &bf[nt >> 1][(nt & 1) * 2]);
        }
    }

#pragma unroll
    for (int nt = 0; nt < 4; nt++) {
        int c = bn0 + wn + nt * 8 + fc;
        float b0 = __ldg(bias + c), b1v = __ldg(bias + c + 1);
#pragma unroll
        for (int mt = 0; mt < 4; mt++) {
            int r = bm0 + wm + mt * 16 + fr;
            float2 o;
            o.x = fmaxf(acc[mt][nt][0] + b0, 0.f);
            o.y = fmaxf(acc[mt][nt][1] + b1v, 0.f);
            *(float2*)(g_feats + (size_t)r * FC + c) = o;
            o.x = fmaxf(acc[mt][nt][2] + b0, 0.f);
            o.y = fmaxf(acc[mt][nt][3] + b1v, 0.f);
            *(float2*)(g_feats + (size_t)(r + 8) * FC + c) = o;
        }
    }
#undef G1_ISSUE
}

// ---------------- build x (fp16 single) ----------------
__global__ void k_makex(const int* __restrict__ attrs) {
    int i = blockIdx.x * blockDim.x + threadIdx.x;
    if (i >= NSAMP * FC) return;
    int n = i >> 9;
    int k = i & (FC - 1);
    bool dist = (attrs[n] >= 5);
    float f0 = g_feats[(size_t)(n * 3 + 0) * FC + k];
    float f1 = g_feats[(size_t)(n * 3 + 1) * FC + k];
    float f2 = g_feats[(size_t)(n * 3 + 2) * FC + k];
    float x0 = dist ? f0 * f1 : f0;
    float x1 = dist ? f1 * f2 : f1;
    size_t base = (size_t)n * (2 * FC);
    g_xf[base + k]      = __float2half_rn(x0);
    g_xf[base + FC + k] = __float2half_rn(x1);
}

// ---------------- GEMM2: h = relu(x @ W1[attr] + b1), 2-term, gathered -----
__global__ __launch_bounds__(256, 2) void k_gemm2(const float* __restrict__ b1)
{
    const int y = blockIdx.y;
    if (y >= g_chunk_off[NATTR]) return;
    int attr = 0;
#pragma unroll
    for (int a = 0; a < NATTR; a++)
        if (y >= g_chunk_off[a]) attr = a;
    const int chunk = y - g_chunk_off[attr];
    const int cnt = g_counts[attr];
    const int base = g_offsets[attr] + chunk * GM2;
    const int nvalid = min(GM2, cnt - chunk * GM2);

    extern __shared__ char smem[];
    __shared__ int sid[GM2];
    const uint32_t sb = (uint32_t)__cvta_generic_to_shared(smem);
    const int tid = threadIdx.x, lane = tid & 31, warp = tid >> 5;
    const int bn0 = blockIdx.x * BN;
    const int wm = (warp >> 2) * 64, wn = (warp & 3) * 32;
    const int fr = lane >> 2, fc = (lane & 3) * 2;
    const int a_row = lane & 15, a_ks = (lane >> 4) * 8;
    const int b_row = (lane & 7) + ((lane >> 3) & 1) * 8, b_cs = (lane >> 4) * 8;

    if (tid < GM2) sid[tid] = (tid < nvalid) ? g_idx[base + tid] : -1;
    __syncthreads();

    const int ar0 = tid >> 2, ac0 = tid & 3;
    const int brow = tid >> 4, bc2 = tid & 15;
    const int s0 = sid[ar0], s1 = sid[ar0 + 64];
    const uint32_t asz0 = (s0 >= 0) ? 16u : 0u;
    const uint32_t asz1 = (s1 >= 0) ? 16u : 0u;
    const __half* sA0 = g_xf + (size_t)(s0 < 0 ? 0 : s0) * (2 * FC) + ac0 * 8;
    const __half* sA1 = g_xf + (size_t)(s1 < 0 ? 0 : s1) * (2 * FC) + ac0 * 8;
    const __half* sBh = g_w1h + (size_t)attr * 2 * FC * FC
                        + (size_t)brow * FC + bn0 + bc2 * 8;
    const __half* sBl = g_w1l + (size_t)attr * 2 * FC * FC
                        + (size_t)brow * FC + bn0 + bc2 * 8;
    const uint32_t dA0 = (uint32_t)(ar0 * (ASTRIDE * 2) + ac0 * 16);
    const uint32_t dA1 = dA0 + 64 * (ASTRIDE * 2);
    const uint32_t dB0 = (uint32_t)(brow * (BSTRIDE * 2) + bc2 * 16);
    const uint32_t dB1 = dB0 + 16 * (BSTRIDE * 2);

    float acc[4][4][4];
#pragma unroll
    for (int mt = 0; mt < 4; mt++)
#pragma unroll
        for (int nt = 0; nt < 4; nt++)
#pragma unroll
            for (int i = 0; i < 4; i++) acc[mt][nt][i] = 0.f;

#define G2_ISSUE(t_) do {                                            \
        const uint32_t s_ = sb + ((t_) % NSTG2) * STAGE2;            \
        const int k0_ = (t_) * BK;                                   \
        cp16z(s_ + OFF2_A + dA0, sA0 + k0_, asz0);                   \
        cp16z(s_ + OFF2_A + dA1, sA1 + k0_, asz1);                   \
        cp16(s_ + OFF2_BH + dB0, sBh + (size_t)k0_ * FC);            \
        cp16(s_ + OFF2_BH + dB1, sBh + (size_t)(k0_ + 16) * FC);     \
        cp16(s_ + OFF2_BL + dB0, sBl + (size_t)k0_ * FC);            \
        cp16(s_ + OFF2_BL + dB1, sBl + (size_t)(k0_ + 16) * FC);     \
        cp_commit();                                                 \
    } while (0)

    G2_ISSUE(0); G2_ISSUE(1);

    for (int t = 0; t < KT2; t++) {
        if (t < KT2 - 1) cp_wait1(); else cp_wait0();
        __syncthreads();
        if (t + 2 < KT2) G2_ISSUE(t + 2);

        const uint32_t s = sb + (t % NSTG2) * STAGE2;
#pragma unroll
        for (int ks = 0; ks < 2; ks++) {
            const int kb = ks * 16;
            uint32_t af[4][4], bfh[2][4], bfl[2][4];
#pragma unroll
            for (int mt = 0; mt < 4; mt++)
                ldsm_x4(af[mt], s + OFF2_A
                        + ((wm + mt * 16 + a_row) * ASTRIDE + kb + a_ks) * 2);
#pragma unroll
            for (int np = 0; np < 2; np++) {
                uint32_t rb = s + OFF2_BH
                    + ((kb + b_row) * BSTRIDE + wn + np * 16 + b_cs) * 2;
                ldsm_x4_t(bfh[np], rb);
                ldsm_x4_t(bfl[np], rb + (OFF2_BL - OFF2_BH));
            }
#pragma unroll
            for (int mt = 0; mt < 4; mt++)
#pragma unroll
                for (int nt = 0; nt < 4; nt++)
                    mma16816(acc[mt][nt], af[mt], &bfh[nt >> 1][(nt & 1) * 2]);
#pragma unroll
            for (int mt = 0; mt < 4; mt++)
#pragma unroll
                for (int nt = 0; nt < 4; nt++)
                    mma16816(acc[mt][nt], af[mt], &bfl[nt >> 1][(nt & 1) * 2]);
        }
    }

#pragma unroll
    for (int nt = 0; nt < 4; nt++) {
        int c = bn0 + wn + nt * 8 + fc;
        float b0 = __ldg(b1 + (size_t)attr * FC + c);
        float b1v = __ldg(b1 + (size_t)attr * FC + c + 1);
#pragma unroll
        for (int mt = 0; mt < 4; mt++) {
            int rA = wm + mt * 16 + fr;
            int sA2 = sid[rA], sB2 = sid[rA + 8];
            if (sA2 >= 0) {
                float2 o;
                o.x = fmaxf(acc[mt][nt][0] + b0, 0.f);
                o.y = fmaxf(acc[mt][nt][1] + b1v, 0.f);
                *(float2*)(g_h + (size_t)sA2 * FC + c) = o;
            }
            if (sB2 >= 0) {
                float2 o;
                o.x = fmaxf(acc[mt][nt][2] + b0, 0.f);
                o.y = fmaxf(acc[mt][nt][3] + b1v, 0.f);
                *(float2*)(g_h + (size_t)sB2 * FC + c) = o;
            }
        }
    }
#undef G2_ISSUE
}

// ---------------- scores = h @ W2[attr] + b2 ----------------
__global__ __launch_bounds__(256) void k_out(
    const int* __restrict__ attrs, const float* __restrict__ W2,
    const float* __restrict__ b2, float* __restrict__ out)
{
    int warp = (blockIdx.x * blockDim.x + threadIdx.x) >> 5;
    int lane = threadIdx.x & 31;
    if (warp >= NSAMP) return;
    int n = warp;
    int a = attrs[n];
    const float* w = W2 + (size_t)a * FC * NANS;
    const float* hp = g_h + (size_t)n * FC;
    float s0 = 0.f, s1 = 0.f;
#pragma unroll
    for (int k = lane; k < FC; k += 32) {
        float hv = hp[k];
        s0 += hv * w[k * 2 + 0];
        s1 += hv * w[k * 2 + 1];
    }
#pragma unroll
    for (int o = 16; o; o >>= 1) {
        s0 += __shfl_down_sync(0xffffffffu, s0, o);
        s1 += __shfl_down_sync(0xffffffffu, s1, o);
    }
    if (lane == 0) {
        out[n * 2 + 0] = s0 + b2[a * 2 + 0];
        out[n * 2 + 1] = s1 + b2[a * 2 + 1];
    }
}

// ---------------- launch ----------------
extern "C" void kernel_launch(void* const* d_in, const int* in_sizes, int n_in,
                              void* d_out, int out_size) {
    const float* img   = (const float*)d_in[0];
    const int*   attrs = (const int*)d_in[1];
    const float* Wcnn  = (const float*)d_in[2];
    const float* bcnn  = (const float*)d_in[3];
    const float* W1    = (const float*)d_in[4];
    const float* b1    = (const float*)d_in[5];
    const float* W2    = (const float*)d_in[6];
    const float* b2    = (const float*)d_in[7];
    float* out = (float*)d_out;

    cudaFuncSetAttribute(k_gemm1, cudaFuncAttributeMaxDynamicSharedMemorySize, SMEM1);
    cudaFuncSetAttribute(k_gemm2, cudaFuncAttributeMaxDynamicSharedMemorySize, SMEM2);

    // prep (slots 1..3), GEMM1 in slot 4 for ncu capture
    k_prep_img<<<(M1 * (IMG_DIM / 4) + 255) / 256, 256>>>(img);
    k_prep_wcnn<<<(IMG_DIM * FC / 4 + 255) / 256, 256>>>(Wcnn);
    k_zero<<<1, 32>>>();

    k_gemm1<<<dim3(FC / BN, M1 / BM), 256, SMEM1>>>(bcnn);

    k_count<<<(NSAMP + 255) / 256, 256>>>(attrs);
    k_scan<<<1, 32>>>();
    k_scatter<<<(NSAMP + 255) / 256, 256>>>(attrs);
    k_prep_w1<<<(NATTR * 2 * FC * FC / 4 + 255) / 256, 256>>>(W1);
    k_makex<<<(NSAMP * FC + 255) / 256, 256>>>(attrs);

    k_gemm2<<<dim3(FC / BN, MAXCH), 256, SMEM2>>>(b1);

    k_out<<<NSAMP / 8, 256>>>(attrs, W2, b2, out);
}

// round 11
// speedup vs baseline: 4.0104x; 1.2582x over previous
#include <cuda_runtime.h>
#include <cuda_fp16.h>
#include <stdint.h>

#define NSAMP 8192
#define MAX_IN 8
#define IMG_DIM 3200
#define FC 512
#define NATTR 7
#define NANS 2
#define M1 (NSAMP * 3)
#define NROW2 (2 * NSAMP)          // rows for slices 0,1 (all samples)

// Common tiling: 128x128 block, BK=32, 256 thr (8 warps = 2M x 4N of 64x32)
#define BM 128
#define BN 128
#define BK 32
#define KT1 (IMG_DIM / BK)         // 100
#define KT2 ((2 * FC) / BK)        // 32
#define ASTRIDE 40                 // fp16 elems per A smem row (80 B)
#define BSTRIDE 136                // fp16 elems per B smem row (272 B)

// GEMM1 (single-term B): stage = A(10240) + B(8704)
#define OFF1_A  0
#define OFF1_B  10240
#define STAGE1  18944
#define NSTG1   4
#define SMEM1   (NSTG1 * STAGE1)   // 75776 -> 2 CTAs/SM

// GEMM2 (two-term B): stage = A(10240) + Bh(8704) + Bl(8704)
#define OFF2_A  0
#define OFF2_BH 10240
#define OFF2_BL 18944
#define STAGE2  27648
#define NSTG2   3
#define SMEM2   (NSTG2 * STAGE2)   // 82944 -> 2 CTAs/SM

#define GM2 128
#define MAXCH (NSAMP / GM2 + NATTR)  // 71

// ---------------- scratch (static device globals) ----------------
__device__ __align__(16) __half g_af[(size_t)M1 * IMG_DIM];   // compact rows
__device__ __align__(16) __half g_wh[(size_t)IMG_DIM * FC];
__device__ __align__(16) __half g_w1h[(size_t)NATTR * 2 * FC * FC];
__device__ __align__(16) __half g_w1l[(size_t)NATTR * 2 * FC * FC];
__device__ __align__(16) __half g_xf[(size_t)NSAMP * 2 * FC];
__device__ __align__(16) float g_feats[(size_t)M1 * FC];      // compact rows
__device__ __align__(16) float g_h[(size_t)NSAMP * FC];
__device__ int g_counts[NATTR];
__device__ int g_offsets[NATTR];
__device__ int g_chunk_off[NATTR + 1];
__device__ int g_idx[NSAMP];
__device__ int g_row2[NSAMP];      // dist sample -> compact f2 row
__device__ int g_nrow;             // compact row count

// ---------------- helpers ----------------
__device__ __forceinline__ uint2 pack4h(float4 v) {
    __half2 a = __floats2half2_rn(v.x, v.y);
    __half2 b = __floats2half2_rn(v.z, v.w);
    uint2 r;
    r.x = *(uint32_t*)&a;
    r.y = *(uint32_t*)&b;
    return r;
}
__device__ __forceinline__ void split4h(float4 v, uint2& hi, uint2& lo) {
    __half2 h01 = __floats2half2_rn(v.x, v.y);
    __half2 h23 = __floats2half2_rn(v.z, v.w);
    float2 f01 = __half22float2(h01);
    float2 f23 = __half22float2(h23);
    __half2 l01 = __floats2half2_rn(v.x - f01.x, v.y - f01.y);
    __half2 l23 = __floats2half2_rn(v.z - f23.x, v.w - f23.y);
    hi.x = *(uint32_t*)&h01; hi.y = *(uint32_t*)&h23;
    lo.x = *(uint32_t*)&l01; lo.y = *(uint32_t*)&l23;
}
__device__ __forceinline__ void mma16816(float* c, const uint32_t* a, const uint32_t* b) {
    asm("mma.sync.aligned.m16n8k16.row.col.f32.f16.f16.f32 "
        "{%0,%1,%2,%3}, {%4,%5,%6,%7}, {%8,%9}, {%0,%1,%2,%3};\n"
        : "+f"(c[0]), "+f"(c[1]), "+f"(c[2]), "+f"(c[3])
        : "r"(a[0]), "r"(a[1]), "r"(a[2]), "r"(a[3]), "r"(b[0]), "r"(b[1]));
}
__device__ __forceinline__ void ldsm_x4(uint32_t* r, uint32_t a) {
    asm volatile("ldmatrix.sync.aligned.m8n8.x4.shared.b16 {%0,%1,%2,%3}, [%4];"
                 : "=r"(r[0]), "=r"(r[1]), "=r"(r[2]), "=r"(r[3]) : "r"(a));
}
__device__ __forceinline__ void ldsm_x4_t(uint32_t* r, uint32_t a) {
    asm volatile("ldmatrix.sync.aligned.m8n8.x4.trans.shared.b16 {%0,%1,%2,%3}, [%4];"
                 : "=r"(r[0]), "=r"(r[1]), "=r"(r[2]), "=r"(r[3]) : "r"(a));
}
__device__ __forceinline__ void cp16(uint32_t dst, const void* src) {
    asm volatile("cp.async.cg.shared.global [%0], [%1], 16;"
                 :: "r"(dst), "l"(src) : "memory");
}
__device__ __forceinline__ void cp16z(uint32_t dst, const void* src, uint32_t sz) {
    asm volatile("cp.async.cg.shared.global [%0], [%1], 16, %2;"
                 :: "r"(dst), "l"(src), "r"(sz) : "memory");
}
__device__ __forceinline__ void cp_commit() {
    asm volatile("cp.async.commit_group;" ::: "memory");
}
__device__ __forceinline__ void cp_wait2() {
    asm volatile("cp.async.wait_group 2;" ::: "memory");
}
__device__ __forceinline__ void cp_wait1() {
    asm volatile("cp.async.wait_group 1;" ::: "memory");
}
__device__ __forceinline__ void cp_wait0() {
    asm volatile("cp.async.wait_group 0;" ::: "memory");
}

// ---------------- fused sort: counts, offsets, scatter, row map ------------
__global__ void k_sort(const int* __restrict__ attrs) {
    __shared__ int scnt[NATTR], scur[NATTR], soff[NATTR];
    const int t = threadIdx.x;
    if (t < NATTR) scnt[t] = 0;
    __syncthreads();
    for (int n = t; n < NSAMP; n += 1024) atomicAdd(&scnt[attrs[n]], 1);
    __syncthreads();
    if (t == 0) {
        int o = 0, co = 0;
        for (int a = 0; a < NATTR; a++) {
            soff[a] = o;
            g_offsets[a] = o;
            g_counts[a] = scnt[a];
            g_chunk_off[a] = co;
            o += scnt[a];
            co += (scnt[a] + GM2 - 1) / GM2;
        }
        g_chunk_off[NATTR] = co;
        g_nrow = NROW2 + scnt[5] + scnt[6];
    }
    if (t < NATTR) scur[t] = 0;
    __syncthreads();
    const int off5 = soff[5];
    for (int n = t; n < NSAMP; n += 1024) {
        int a = attrs[n];
        int p = atomicAdd(&scur[a], 1);
        int pos = soff[a] + p;
        g_idx[pos] = n;
        if (a >= 5) g_row2[n] = NROW2 + (pos - off5);
    }
}

// ---------------- prep kernels ----------------
// compact-row img convert: rows [0, 2N) = (n, s=row&1); rows >= 2N = dist f2
__global__ void k_prep_img(const float* __restrict__ img) {
    const int CPR = IMG_DIM / 4;
    int idx = blockIdx.x * blockDim.x + threadIdx.x;
    if (idx >= M1 * CPR) return;
    int row = idx / CPR;
    if (row >= g_nrow) return;
    int c = idx - row * CPR;
    int n, s;
    if (row < NROW2) { n = row >> 1; s = row & 1; }
    else             { n = g_idx[g_offsets[5] + (row - NROW2)]; s = 2; }
    float4 v = *(const float4*)(img + (size_t)(n * MAX_IN + s) * IMG_DIM + c * 4);
    *(uint2*)(g_af + (size_t)row * IMG_DIM + c * 4) = pack4h(v);
}
__global__ void k_prep_wcnn(const float* __restrict__ W) {
    int idx = blockIdx.x * blockDim.x + threadIdx.x;
    if (idx >= IMG_DIM * FC / 4) return;
    float4 v = *(const float4*)(W + (size_t)idx * 4);
    *(uint2*)(g_wh + (size_t)idx * 4) = pack4h(v);
}
__global__ void k_prep_w1(const float* __restrict__ W1) {
    int idx = blockIdx.x * blockDim.x + threadIdx.x;
    if (idx >= NATTR * 2 * FC * FC / 4) return;
    float4 v = *(const float4*)(W1 + (size_t)idx * 4);
    uint2 hi, lo;
    split4h(v, hi, lo);
    *(uint2*)(g_w1h + (size_t)idx * 4) = hi;
    *(uint2*)(g_w1l + (size_t)idx * 4) = lo;
}

// ---------------- GEMM1: feats = relu(imgC @ Wcnn + b), single-term fp16 ---
__global__ __launch_bounds__(256, 2) void k_gemm1(const float* __restrict__ bias)
{
    const int bn0 = blockIdx.x * BN, bm0 = blockIdx.y * BM;
    if (bm0 >= g_nrow) return;     // compact-row early exit (uniform)

    extern __shared__ char smem[];
    const uint32_t sb = (uint32_t)__cvta_generic_to_shared(smem);
    const int tid = threadIdx.x, lane = tid & 31, warp = tid >> 5;
    const int wm = (warp >> 2) * 64, wn = (warp & 3) * 32;
    const int fr = lane >> 2, fc = (lane & 3) * 2;
    const int a_row = lane & 15, a_ks = (lane >> 4) * 8;
    const int b_row = (lane & 7) + ((lane >> 3) & 1) * 8, b_cs = (lane >> 4) * 8;

    const int ar0 = tid >> 2, ac0 = tid & 3;
    const int brow = tid >> 4, bc2 = tid & 15;
    const __half* sA0 = g_af + (size_t)(bm0 + ar0) * IMG_DIM + ac0 * 8;
    const __half* sA1 = g_af + (size_t)(bm0 + ar0 + 64) * IMG_DIM + ac0 * 8;
    const __half* sB  = g_wh + (size_t)brow * FC + bn0 + bc2 * 8;
    const uint32_t dA0 = (uint32_t)(ar0 * (ASTRIDE * 2) + ac0 * 16);
    const uint32_t dA1 = dA0 + 64 * (ASTRIDE * 2);
    const uint32_t dB0 = (uint32_t)(brow * (BSTRIDE * 2) + bc2 * 16);
    const uint32_t dB1 = dB0 + 16 * (BSTRIDE * 2);

    float acc[4][4][4];
#pragma unroll
    for (int mt = 0; mt < 4; mt++)
#pragma unroll
        for (int nt = 0; nt < 4; nt++)
#pragma unroll
            for (int i = 0; i < 4; i++) acc[mt][nt][i] = 0.f;

#define G1_ISSUE(t_) do {                                            \
        const uint32_t s_ = sb + ((t_) % NSTG1) * STAGE1;            \
        const int k0_ = (t_) * BK;                                   \
        cp16(s_ + OFF1_A + dA0, sA0 + k0_);                          \
        cp16(s_ + OFF1_A + dA1, sA1 + k0_);                          \
        cp16(s_ + OFF1_B + dB0, sB + (size_t)k0_ * FC);              \
        cp16(s_ + OFF1_B + dB1, sB + (size_t)(k0_ + 16) * FC);       \
        cp_commit();                                                 \
    } while (0)

    G1_ISSUE(0); G1_ISSUE(1); G1_ISSUE(2);

    for (int t = 0; t < KT1; t++) {
        if (t < KT1 - 2) cp_wait2();
        else if (t == KT1 - 2) cp_wait1();
        else cp_wait0();
        __syncthreads();
        if (t + 3 < KT1) G1_ISSUE(t + 3);

        const uint32_t s = sb + (t % NSTG1) * STAGE1;
#pragma unroll
        for (int ks = 0; ks < 2; ks++) {
            const int kb = ks * 16;
            uint32_t af[4][4], bf[2][4];
#pragma unroll
            for (int mt = 0; mt < 4; mt++)
                ldsm_x4(af[mt], s + OFF1_A
                        + ((wm + mt * 16 + a_row) * ASTRIDE + kb + a_ks) * 2);
#pragma unroll
            for (int np = 0; np < 2; np++)
                ldsm_x4_t(bf[np], s + OFF1_B
                          + ((kb + b_row) * BSTRIDE + wn + np * 16 + b_cs) * 2);
#pragma unroll
            for (int mt = 0; mt < 4; mt++)
#pragma unroll
                for (int nt = 0; nt < 4; nt++)
                    mma16816(acc[mt][nt], af[mt], &bf[nt >> 1][(nt & 1) * 2]);
        }
    }

#pragma unroll
    for (int nt = 0; nt < 4; nt++) {
        int c = bn0 + wn + nt * 8 + fc;
        float b0 = __ldg(bias + c), b1v = __ldg(bias + c + 1);
#pragma unroll
        for (int mt = 0; mt < 4; mt++) {
            int r = bm0 + wm + mt * 16 + fr;
            float2 o;
            o.x = fmaxf(acc[mt][nt][0] + b0, 0.f);
            o.y = fmaxf(acc[mt][nt][1] + b1v, 0.f);
            *(float2*)(g_feats + (size_t)r * FC + c) = o;
            o.x = fmaxf(acc[mt][nt][2] + b0, 0.f);
            o.y = fmaxf(acc[mt][nt][3] + b1v, 0.f);
            *(float2*)(g_feats + (size_t)(r + 8) * FC + c) = o;
        }
    }
#undef G1_ISSUE
}

// ---------------- build x (fp16), compact-row feats ----------------
__global__ void k_makex(const int* __restrict__ attrs) {
    int i = blockIdx.x * blockDim.x + threadIdx.x;
    if (i >= NSAMP * FC) return;
    int n = i >> 9;
    int k = i & (FC - 1);
    bool dist = (attrs[n] >= 5);
    float f0 = g_feats[(size_t)(2 * n) * FC + k];
    float f1 = g_feats[(size_t)(2 * n + 1) * FC + k];
    float x0, x1;
    if (dist) {
        float f2 = g_feats[(size_t)g_row2[n] * FC + k];
        x0 = f0 * f1;
        x1 = f1 * f2;
    } else {
        x0 = f0;
        x1 = f1;
    }
    size_t base = (size_t)n * (2 * FC);
    g_xf[base + k]      = __float2half_rn(x0);
    g_xf[base + FC + k] = __float2half_rn(x1);
}

// ---------------- GEMM2: h = relu(x @ W1[attr] + b1), 2-term, gathered -----
__global__ __launch_bounds__(256, 2) void k_gemm2(const float* __restrict__ b1)
{
    const int y = blockIdx.y;
    if (y >= g_chunk_off[NATTR]) return;
    int attr = 0;
#pragma unroll
    for (int a = 0; a < NATTR; a++)
        if (y >= g_chunk_off[a]) attr = a;
    const int chunk = y - g_chunk_off[attr];
    const int cnt = g_counts[attr];
    const int base = g_offsets[attr] + chunk * GM2;
    const int nvalid = min(GM2, cnt - chunk * GM2);

    extern __shared__ char smem[];
    __shared__ int sid[GM2];
    const uint32_t sb = (uint32_t)__cvta_generic_to_shared(smem);
    const int tid = threadIdx.x, lane = tid & 31, warp = tid >> 5;
    const int bn0 = blockIdx.x * BN;
    const int wm = (warp >> 2) * 64, wn = (warp & 3) * 32;
    const int fr = lane >> 2, fc = (lane & 3) * 2;
    const int a_row = lane & 15, a_ks = (lane >> 4) * 8;
    const int b_row = (lane & 7) + ((lane >> 3) & 1) * 8, b_cs = (lane >> 4) * 8;

    if (tid < GM2) sid[tid] = (tid < nvalid) ? g_idx[base + tid] : -1;
    __syncthreads();

    const int ar0 = tid >> 2, ac0 = tid & 3;
    const int brow = tid >> 4, bc2 = tid & 15;
    const int s0 = sid[ar0], s1 = sid[ar0 + 64];
    const uint32_t asz0 = (s0 >= 0) ? 16u : 0u;
    const uint32_t asz1 = (s1 >= 0) ? 16u : 0u;
    const __half* sA0 = g_xf + (size_t)(s0 < 0 ? 0 : s0) * (2 * FC) + ac0 * 8;
    const __half* sA1 = g_xf + (size_t)(s1 < 0 ? 0 : s1) * (2 * FC) + ac0 * 8;
    const __half* sBh = g_w1h + (size_t)attr * 2 * FC * FC
                        + (size_t)brow * FC + bn0 + bc2 * 8;
    const __half* sBl = g_w1l + (size_t)attr * 2 * FC * FC
                        + (size_t)brow * FC + bn0 + bc2 * 8;
    const uint32_t dA0 = (uint32_t)(ar0 * (ASTRIDE * 2) + ac0 * 16);
    const uint32_t dA1 = dA0 + 64 * (ASTRIDE * 2);
    const uint32_t dB0 = (uint32_t)(brow * (BSTRIDE * 2) + bc2 * 16);
    const uint32_t dB1 = dB0 + 16 * (BSTRIDE * 2);

    float acc[4][4][4];
#pragma unroll
    for (int mt = 0; mt < 4; mt++)
#pragma unroll
        for (int nt = 0; nt < 4; nt++)
#pragma unroll
            for (int i = 0; i < 4; i++) acc[mt][nt][i] = 0.f;

#define G2_ISSUE(t_) do {                                            \
        const uint32_t s_ = sb + ((t_) % NSTG2) * STAGE2;            \
        const int k0_ = (t_) * BK;                                   \
        cp16z(s_ + OFF2_A + dA0, sA0 + k0_, asz0);                   \
        cp16z(s_ + OFF2_A + dA1, sA1 + k0_, asz1);                   \
        cp16(s_ + OFF2_BH + dB0, sBh + (size_t)k0_ * FC);            \
        cp16(s_ + OFF2_BH + dB1, sBh + (size_t)(k0_ + 16) * FC);     \
        cp16(s_ + OFF2_BL + dB0, sBl + (size_t)k0_ * FC);            \
        cp16(s_ + OFF2_BL + dB1, sBl + (size_t)(k0_ + 16) * FC);     \
        cp_commit();                                                 \
    } while (0)

    G2_ISSUE(0); G2_ISSUE(1);

    for (int t = 0; t < KT2; t++) {
        if (t < KT2 - 1) cp_wait1(); else cp_wait0();
        __syncthreads();
        if (t + 2 < KT2) G2_ISSUE(t + 2);

        const uint32_t s = sb + (t % NSTG2) * STAGE2;
#pragma unroll
        for (int ks = 0; ks < 2; ks++) {
            const int kb = ks * 16;
            uint32_t af[4][4], bfh[2][4], bfl[2][4];
#pragma unroll
            for (int mt = 0; mt < 4; mt++)
                ldsm_x4(af[mt], s + OFF2_A
                        + ((wm + mt * 16 + a_row) * ASTRIDE + kb + a_ks) * 2);
#pragma unroll
            for (int np = 0; np < 2; np++) {
                uint32_t rb = s + OFF2_BH
                    + ((kb + b_row) * BSTRIDE + wn + np * 16 + b_cs) * 2;
                ldsm_x4_t(bfh[np], rb);
                ldsm_x4_t(bfl[np], rb + (OFF2_BL - OFF2_BH));
            }
#pragma unroll
            for (int mt = 0; mt < 4; mt++)
#pragma unroll
                for (int nt = 0; nt < 4; nt++)
                    mma16816(acc[mt][nt], af[mt], &bfh[nt >> 1][(nt & 1) * 2]);
#pragma unroll
            for (int mt = 0; mt < 4; mt++)
#pragma unroll
                for (int nt = 0; nt < 4; nt++)
                    mma16816(acc[mt][nt], af[mt], &bfl[nt >> 1][(nt & 1) * 2]);
        }
    }

#pragma unroll
    for (int nt = 0; nt < 4; nt++) {
        int c = bn0 + wn + nt * 8 + fc;
        float b0 = __ldg(b1 + (size_t)attr * FC + c);
        float b1v = __ldg(b1 + (size_t)attr * FC + c + 1);
#pragma unroll
        for (int mt = 0; mt < 4; mt++) {
            int rA = wm + mt * 16 + fr;
            int sA2 = sid[rA], sB2 = sid[rA + 8];
            if (sA2 >= 0) {
                float2 o;
                o.x = fmaxf(acc[mt][nt][0] + b0, 0.f);
                o.y = fmaxf(acc[mt][nt][1] + b1v, 0.f);
                *(float2*)(g_h + (size_t)sA2 * FC + c) = o;
            }
            if (sB2 >= 0) {
                float2 o;
                o.x = fmaxf(acc[mt][nt][2] + b0, 0.f);
                o.y = fmaxf(acc[mt][nt][3] + b1v, 0.f);
                *(float2*)(g_h + (size_t)sB2 * FC + c) = o;
            }
        }
    }
#undef G2_ISSUE
}

// ---------------- scores = h @ W2[attr] + b2 ----------------
__global__ __launch_bounds__(256) void k_out(
    const int* __restrict__ attrs, const float* __restrict__ W2,
    const float* __restrict__ b2, float* __restrict__ out)
{
    int warp = (blockIdx.x * blockDim.x + threadIdx.x) >> 5;
    int lane = threadIdx.x & 31;
    if (warp >= NSAMP) return;
    int n = warp;
    int a = attrs[n];
    const float* w = W2 + (size_t)a * FC * NANS;
    const float* hp = g_h + (size_t)n * FC;
    float s0 = 0.f, s1 = 0.f;
#pragma unroll
    for (int k = lane; k < FC; k += 32) {
        float hv = hp[k];
        s0 += hv * w[k * 2 + 0];
        s1 += hv * w[k * 2 + 1];
    }
#pragma unroll
    for (int o = 16; o; o >>= 1) {
        s0 += __shfl_down_sync(0xffffffffu, s0, o);
        s1 += __shfl_down_sync(0xffffffffu, s1, o);
    }
    if (lane == 0) {
        out[n * 2 + 0] = s0 + b2[a * 2 + 0];
        out[n * 2 + 1] = s1 + b2[a * 2 + 1];
    }
}

// ---------------- launch ----------------
extern "C" void kernel_launch(void* const* d_in, const int* in_sizes, int n_in,
                              void* d_out, int out_size) {
    const float* img   = (const float*)d_in[0];
    const int*   attrs = (const int*)d_in[1];
    const float* Wcnn  = (const float*)d_in[2];
    const float* bcnn  = (const float*)d_in[3];
    const float* W1    = (const float*)d_in[4];
    const float* b1    = (const float*)d_in[5];
    const float* W2    = (const float*)d_in[6];
    const float* b2    = (const float*)d_in[7];
    float* out = (float*)d_out;

    cudaFuncSetAttribute(k_gemm1, cudaFuncAttributeMaxDynamicSharedMemorySize, SMEM1);
    cudaFuncSetAttribute(k_gemm2, cudaFuncAttributeMaxDynamicSharedMemorySize, SMEM2);

    // slot 1..3: sort + prep, slot 4: GEMM1 (ncu capture slot)
    k_sort<<<1, 1024>>>(attrs);
    k_prep_img<<<(M1 * (IMG_DIM / 4) + 255) / 256, 256>>>(img);
    k_prep_wcnn<<<(IMG_DIM * FC / 4 + 255) / 256, 256>>>(Wcnn);

    k_gemm1<<<dim3(FC / BN, M1 / BM), 256, SMEM1>>>(bcnn);

    k_prep_w1<<<(NATTR * 2 * FC * FC / 4 + 255) / 256, 256>>>(W1);
    k_makex<<<(NSAMP * FC + 255) / 256, 256>>>(attrs);

    k_gemm2<<<dim3(FC / BN, MAXCH), 256, SMEM2>>>(b1);

    k_out<<<NSAMP / 8, 256>>>(attrs, W2, b2, out);
}